// round 13
// baseline (speedup 1.0000x reference)
#include <cuda_runtime.h>
#include <cuda_bf16.h>
#include <math.h>

#define Nn 1024
#define Dd 1024
#define Gg 16

// Scratch (allocation-free rule: __device__ globals). Packed bf16 hi/lo pairs.
__device__ unsigned g_qh[Nn * 512], g_ql[Nn * 512];   // q [i][d/2]
__device__ unsigned g_kh[Nn * 512], g_kl[Nn * 512];   // k [j][d/2]
__device__ unsigned g_vh[Nn * 512], g_vl[Nn * 512];   // v2 [j][o/2]
__device__ float g_aff[(size_t)Nn * Gg * Nn];         // aff -> overwritten with weighted logits

__device__ __forceinline__ unsigned f2tf(float x) {
    unsigned u; asm("cvt.rna.tf32.f32 %0, %1;" : "=r"(u) : "f"(x)); return u;
}
__device__ __forceinline__ float ftanh(float x) {
    float y; asm("tanh.approx.f32 %0, %1;" : "=f"(y) : "f"(x)); return y;
}
__device__ __forceinline__ void mma_tf32(float* c,
    unsigned a0, unsigned a1, unsigned a2, unsigned a3,
    unsigned b0, unsigned b1) {
    asm volatile(
        "mma.sync.aligned.m16n8k8.row.col.f32.tf32.tf32.f32 "
        "{%0,%1,%2,%3}, {%4,%5,%6,%7}, {%8,%9}, {%0,%1,%2,%3};\n"
        : "+f"(c[0]), "+f"(c[1]), "+f"(c[2]), "+f"(c[3])
        : "r"(a0), "r"(a1), "r"(a2), "r"(a3), "r"(b0), "r"(b1));
}
__device__ __forceinline__ void mma_bf16(float* c,
    unsigned a0, unsigned a1, unsigned a2, unsigned a3,
    unsigned b0, unsigned b1) {
    asm volatile(
        "mma.sync.aligned.m16n8k16.row.col.f32.bf16.bf16.f32 "
        "{%0,%1,%2,%3}, {%4,%5,%6,%7}, {%8,%9}, {%0,%1,%2,%3};\n"
        : "+f"(c[0]), "+f"(c[1]), "+f"(c[2]), "+f"(c[3])
        : "r"(a0), "r"(a1), "r"(a2), "r"(a3), "r"(b0), "r"(b1));
}
__device__ __forceinline__ unsigned sptr(const void* p) {
    return (unsigned)__cvta_generic_to_shared(p);
}
__device__ __forceinline__ void ldsm_x4(unsigned& r0, unsigned& r1, unsigned& r2, unsigned& r3, unsigned a) {
    asm volatile("ldmatrix.sync.aligned.m8n8.x4.shared.b16 {%0,%1,%2,%3}, [%4];"
        : "=r"(r0), "=r"(r1), "=r"(r2), "=r"(r3) : "r"(a));
}
__device__ __forceinline__ void ldsm_x2(unsigned& r0, unsigned& r1, unsigned a) {
    asm volatile("ldmatrix.sync.aligned.m8n8.x2.shared.b16 {%0,%1}, [%2];"
        : "=r"(r0), "=r"(r1) : "r"(a));
}
__device__ __forceinline__ void ldsm_x2t(unsigned& r0, unsigned& r1, unsigned a) {
    asm volatile("ldmatrix.sync.aligned.m8n8.x2.trans.shared.b16 {%0,%1}, [%2];"
        : "=r"(r0), "=r"(r1) : "r"(a));
}
// bf16 hi/lo split of a pair (a->low half, b->high half)
__device__ __forceinline__ void pack2(float a, float b, unsigned& hi, unsigned& lo) {
    __nv_bfloat16 ba = __float2bfloat16(a), bb = __float2bfloat16(b);
    hi = ((unsigned)__bfloat16_as_ushort(bb) << 16) | (unsigned)__bfloat16_as_ushort(ba);
    __nv_bfloat16 la = __float2bfloat16(a - __bfloat162float(ba));
    __nv_bfloat16 lb = __float2bfloat16(b - __bfloat162float(bb));
    lo = ((unsigned)__bfloat16_as_ushort(lb) << 16) | (unsigned)__bfloat16_as_ushort(la);
}

// ---------------------------------------------------------------------------
// K1: three 1024^3 GEMMs via 3-pass bf16 mma (z=0: Q, z=1: K, z=2: V2)
// (R11 winner: LDG -> pack2 -> STS, double-buffered)
// ---------------------------------------------------------------------------
#define K1_AS 1536   // 128*12 b32 per A buffer
#define K1_BS 1088   // 16*68 b32 per B buffer

__global__ void __launch_bounds__(256, 2) k_gemm3(
    const float* __restrict__ roi,
    const float* __restrict__ Wq, const float* __restrict__ bq,
    const float* __restrict__ Wk, const float* __restrict__ bk,
    const float* __restrict__ Wout)
{
    extern __shared__ unsigned smu[];
    unsigned* Ah = smu;
    unsigned* Al = Ah + 2 * K1_AS;
    unsigned* Bh = Al + 2 * K1_AS;
    unsigned* Bl = Bh + 2 * K1_BS;

    const int z = blockIdx.z;
    const int rowBase = blockIdx.y * 128, colBase = blockIdx.x * 128;
    const int tid = threadIdx.x, lane = tid & 31, wid = tid >> 5;
    const int g = lane >> 2, tg = lane & 3;
    const int m_off = (wid >> 2) * 64, n_off = (wid & 3) * 32;
    const float* Bm = (z == 0) ? Wq : (z == 1) ? Wk : Wout;

    float acc[4][4][4] = {};
    const int larow = lane & 15, lcol4 = (lane >> 4) * 4;
    float4 aReg[2], bReg[2];

    {
        const int k0 = 0;
        #pragma unroll
        for (int it = 0; it < 2; it++) {
            int idx = tid + it * 256;
            int r = idx >> 2, c4 = idx & 3;
            aReg[it] = *(const float4*)&roi[(size_t)(rowBase + r) * 1024 + k0 + c4 * 4];
        }
        #pragma unroll
        for (int it = 0; it < 2; it++) {
            int idx = tid + it * 256;
            int kr = idx >> 5, c4 = idx & 31;
            int col = colBase + c4 * 4;
            const float* src;
            if (z < 2) src = &Bm[(size_t)(k0 + kr) * 1024 + col];
            else { int gg = col >> 6, oo = col & 63; src = &Bm[((size_t)gg * 1024 + (k0 + kr)) * 64 + oo]; }
            bReg[it] = *(const float4*)src;
        }
        #pragma unroll
        for (int it = 0; it < 2; it++) {
            int idx = tid + it * 256;
            int r = idx >> 2, c4 = idx & 3;
            unsigned h0, l0, h1, l1;
            pack2(aReg[it].x, aReg[it].y, h0, l0);
            pack2(aReg[it].z, aReg[it].w, h1, l1);
            Ah[r * 12 + c4 * 2] = h0; Ah[r * 12 + c4 * 2 + 1] = h1;
            Al[r * 12 + c4 * 2] = l0; Al[r * 12 + c4 * 2 + 1] = l1;
        }
        #pragma unroll
        for (int it = 0; it < 2; it++) {
            int idx = tid + it * 256;
            int kr = idx >> 5, c4 = idx & 31;
            unsigned h0, l0, h1, l1;
            pack2(bReg[it].x, bReg[it].y, h0, l0);
            pack2(bReg[it].z, bReg[it].w, h1, l1);
            Bh[kr * 68 + c4 * 2] = h0; Bh[kr * 68 + c4 * 2 + 1] = h1;
            Bl[kr * 68 + c4 * 2] = l0; Bl[kr * 68 + c4 * 2 + 1] = l1;
        }
    }
    __syncthreads();

    for (int s = 0; s < 64; s++) {
        const int buf = s & 1;
        if (s < 63) {
            const int k0 = (s + 1) * 16;
            #pragma unroll
            for (int it = 0; it < 2; it++) {
                int idx = tid + it * 256;
                int r = idx >> 2, c4 = idx & 3;
                aReg[it] = *(const float4*)&roi[(size_t)(rowBase + r) * 1024 + k0 + c4 * 4];
            }
            #pragma unroll
            for (int it = 0; it < 2; it++) {
                int idx = tid + it * 256;
                int kr = idx >> 5, c4 = idx & 31;
                int col = colBase + c4 * 4;
                const float* src;
                if (z < 2) src = &Bm[(size_t)(k0 + kr) * 1024 + col];
                else { int gg = col >> 6, oo = col & 63; src = &Bm[((size_t)gg * 1024 + (k0 + kr)) * 64 + oo]; }
                bReg[it] = *(const float4*)src;
            }
        }

        const unsigned* ah_b = Ah + buf * K1_AS;
        const unsigned* al_b = Al + buf * K1_AS;
        const unsigned* bh_b = Bh + buf * K1_BS;
        const unsigned* bl_b = Bl + buf * K1_BS;

        unsigned ah[4][4], al[4][4];
        #pragma unroll
        for (int mt = 0; mt < 4; mt++) {
            const int rb = m_off + mt * 16;
            ldsm_x4(ah[mt][0], ah[mt][1], ah[mt][2], ah[mt][3],
                    sptr(&ah_b[(rb + larow) * 12 + lcol4]));
            ldsm_x4(al[mt][0], al[mt][1], al[mt][2], al[mt][3],
                    sptr(&al_b[(rb + larow) * 12 + lcol4]));
        }
        #pragma unroll
        for (int nt = 0; nt < 4; nt++) {
            const int nbc = (n_off >> 1) + nt * 4;
            unsigned bh0, bh1, bl0, bl1;
            ldsm_x2t(bh0, bh1, sptr(&bh_b[larow * 68 + nbc]));
            ldsm_x2t(bl0, bl1, sptr(&bl_b[larow * 68 + nbc]));
            #pragma unroll
            for (int mt = 0; mt < 4; mt++) {
                mma_bf16(acc[mt][nt], ah[mt][0], ah[mt][1], ah[mt][2], ah[mt][3], bl0, bl1);
                mma_bf16(acc[mt][nt], al[mt][0], al[mt][1], al[mt][2], al[mt][3], bh0, bh1);
                mma_bf16(acc[mt][nt], ah[mt][0], ah[mt][1], ah[mt][2], ah[mt][3], bh0, bh1);
            }
        }

        if (s < 63) {
            unsigned* AhN = Ah + (buf ^ 1) * K1_AS;
            unsigned* AlN = Al + (buf ^ 1) * K1_AS;
            unsigned* BhN = Bh + (buf ^ 1) * K1_BS;
            unsigned* BlN = Bl + (buf ^ 1) * K1_BS;
            #pragma unroll
            for (int it = 0; it < 2; it++) {
                int idx = tid + it * 256;
                int r = idx >> 2, c4 = idx & 3;
                unsigned h0, l0, h1, l1;
                pack2(aReg[it].x, aReg[it].y, h0, l0);
                pack2(aReg[it].z, aReg[it].w, h1, l1);
                AhN[r * 12 + c4 * 2] = h0; AhN[r * 12 + c4 * 2 + 1] = h1;
                AlN[r * 12 + c4 * 2] = l0; AlN[r * 12 + c4 * 2 + 1] = l1;
            }
            #pragma unroll
            for (int it = 0; it < 2; it++) {
                int idx = tid + it * 256;
                int kr = idx >> 5, c4 = idx & 31;
                unsigned h0, l0, h1, l1;
                pack2(bReg[it].x, bReg[it].y, h0, l0);
                pack2(bReg[it].z, bReg[it].w, h1, l1);
                BhN[kr * 68 + c4 * 2] = h0; BhN[kr * 68 + c4 * 2 + 1] = h1;
                BlN[kr * 68 + c4 * 2] = l0; BlN[kr * 68 + c4 * 2 + 1] = l1;
            }
        }
        __syncthreads();
    }

    // epilogue: add bias, pack to bf16 hi/lo, store u32 pairs
    #pragma unroll
    for (int mt = 0; mt < 4; mt++) {
        #pragma unroll
        for (int nt = 0; nt < 4; nt++) {
            const int row = rowBase + m_off + mt * 16 + g;
            const int col = colBase + n_off + nt * 8 + 2 * tg;
            const size_t p0 = (size_t)row * 512 + (col >> 1);
            const size_t p1 = (size_t)(row + 8) * 512 + (col >> 1);
            float v0 = acc[mt][nt][0], v1 = acc[mt][nt][1];
            float v2 = acc[mt][nt][2], v3 = acc[mt][nt][3];
            unsigned h, l;
            if (z == 0) {
                float b0 = bq[col], b1 = bq[col + 1];
                pack2(v0 + b0, v1 + b1, h, l); g_qh[p0] = h; g_ql[p0] = l;
                pack2(v2 + b0, v3 + b1, h, l); g_qh[p1] = h; g_ql[p1] = l;
            } else if (z == 1) {
                float b0 = bk[col], b1 = bk[col + 1];
                pack2(v0 + b0, v1 + b1, h, l); g_kh[p0] = h; g_kl[p0] = l;
                pack2(v2 + b0, v3 + b1, h, l); g_kh[p1] = h; g_kl[p1] = l;
            } else {
                pack2(v0, v1, h, l); g_vh[p0] = h; g_vl[p0] = l;
                pack2(v2, v3, h, l); g_vh[p1] = h; g_vl[p1] = l;
            }
        }
    }
}

// ---------------------------------------------------------------------------
// K2: PE MLP via tf32 mma; tanh.approx. (unchanged)
// ---------------------------------------------------------------------------
__global__ void __launch_bounds__(256, 2) k_pe(
    const float* __restrict__ pe,
    const float* __restrict__ W1, const float* __restrict__ b1,
    const float* __restrict__ W2, const float* __restrict__ b2)
{
    extern __shared__ float sm2[];
    float* H    = sm2;
    float* W1sT = H + 17408;
    float* W2sT = W1sT + 4352;
    float* bb1  = W2sT + 1088;
    float* bb2  = bb1 + 64;

    const int tid = threadIdx.x, lane = tid & 31, wid = tid >> 5;
    const int g = lane >> 2, tg = lane & 3;
    const int arow = lane & 15, acolo = (lane >> 4) * 4;
    const int brow = lane & 7, bcolo = ((lane >> 3) & 1) * 4;

    for (int l = tid; l < 4096; l += 256) {
        int k = l >> 6, n = l & 63;
        W1sT[n * 68 + k] = __uint_as_float(f2tf(W1[l]));
    }
    for (int l = tid; l < 1024; l += 256) {
        int k = l >> 4, n = l & 15;
        W2sT[n * 68 + k] = __uint_as_float(f2tf(W2[l]));
    }
    if (tid < 64) bb1[tid] = b1[tid];
    if (tid < 16) bb2[tid] = b2[tid];

    const size_t base = (size_t)blockIdx.x * 256 * 64;
    #pragma unroll
    for (int it = 0; it < 16; it++) {
        int idx = tid + it * 256;
        int r = idx >> 4, c4 = idx & 15;
        float4 v = *(const float4*)&pe[base + (size_t)idx * 4];
        float4 w;
        w.x = __uint_as_float(f2tf(v.x)); w.y = __uint_as_float(f2tf(v.y));
        w.z = __uint_as_float(f2tf(v.z)); w.w = __uint_as_float(f2tf(v.w));
        *(float4*)&H[r * 68 + c4 * 4] = w;
    }
    __syncthreads();

    const int rb0 = wid * 32;
    float acc[2][8][4] = {};
    #pragma unroll
    for (int kt = 0; kt < 8; kt++) {
        const int kb = kt * 8;
        unsigned a[2][4];
        #pragma unroll
        for (int mt = 0; mt < 2; mt++) {
            ldsm_x4(a[mt][0], a[mt][1], a[mt][2], a[mt][3],
                    sptr(&H[(rb0 + mt * 16 + arow) * 68 + kb + acolo]));
        }
        #pragma unroll
        for (int nt = 0; nt < 8; nt++) {
            unsigned b0, b1r;
            ldsm_x2(b0, b1r, sptr(&W1sT[(nt * 8 + brow) * 68 + kb + bcolo]));
            mma_tf32(acc[0][nt], a[0][0], a[0][1], a[0][2], a[0][3], b0, b1r);
            mma_tf32(acc[1][nt], a[1][0], a[1][1], a[1][2], a[1][3], b0, b1r);
        }
    }

    #pragma unroll
    for (int mt = 0; mt < 2; mt++) {
        const int r0 = rb0 + mt * 16 + g;
        #pragma unroll
        for (int nt = 0; nt < 8; nt++) {
            const int col = nt * 8 + 2 * tg;
            float h0 = ftanh(acc[mt][nt][0] + bb1[col]);
            float h1 = ftanh(acc[mt][nt][1] + bb1[col + 1]);
            float h2 = ftanh(acc[mt][nt][2] + bb1[col]);
            float h3 = ftanh(acc[mt][nt][3] + bb1[col + 1]);
            H[r0 * 68 + col]       = __uint_as_float(f2tf(h0));
            H[r0 * 68 + col + 1]   = __uint_as_float(f2tf(h1));
            H[(r0 + 8) * 68 + col]     = __uint_as_float(f2tf(h2));
            H[(r0 + 8) * 68 + col + 1] = __uint_as_float(f2tf(h3));
        }
    }
    __syncwarp();

    float acc2[2][2][4] = {};
    #pragma unroll
    for (int kt = 0; kt < 8; kt++) {
        const int kb = kt * 8;
        unsigned a[2][4];
        #pragma unroll
        for (int mt = 0; mt < 2; mt++) {
            ldsm_x4(a[mt][0], a[mt][1], a[mt][2], a[mt][3],
                    sptr(&H[(rb0 + mt * 16 + arow) * 68 + kb + acolo]));
        }
        #pragma unroll
        for (int nt = 0; nt < 2; nt++) {
            unsigned b0, b1r;
            ldsm_x2(b0, b1r, sptr(&W2sT[(nt * 8 + brow) * 68 + kb + bcolo]));
            mma_tf32(acc2[0][nt], a[0][0], a[0][1], a[0][2], a[0][3], b0, b1r);
            mma_tf32(acc2[1][nt], a[1][0], a[1][1], a[1][2], a[1][3], b0, b1r);
        }
    }

    const int growBase = blockIdx.x * 256;
    const int i = growBase >> 10;
    #pragma unroll
    for (int mt = 0; mt < 2; mt++) {
        #pragma unroll
        for (int nt = 0; nt < 2; nt++) {
            #pragma unroll
            for (int e = 0; e < 4; e++) {
                int grow = growBase + rb0 + mt * 16 + g + ((e >= 2) ? 8 : 0);
                int j = grow & 1023;
                int col = nt * 8 + 2 * tg + (e & 1);
                g_aff[((size_t)i * 16 + col) * 1024 + j] = acc2[mt][nt][e] + bb2[col];
            }
        }
    }
}

// ---------------------------------------------------------------------------
// K3a: weighted logits W = aff * (Q K^T / 8) in place. 128x128 tiles.
// 8 warps = 4(m) x 2(n): warp tile 32 x 64. smem 72 KB -> 2 CTAs/SM.
// ---------------------------------------------------------------------------
#define LGT_SMEM_U (4 * 4608)

__global__ void __launch_bounds__(256) k_logits()
{
    extern __shared__ unsigned smlu[];
    unsigned* Qh = smlu;           // [128][36]
    unsigned* Ql = Qh + 4608;
    unsigned* Kh = Ql + 4608;
    unsigned* Kl = Kh + 4608;

    const int gblk = blockIdx.z;
    const int i0 = blockIdx.y * 128, j0 = blockIdx.x * 128;
    const int tid = threadIdx.x, lane = tid & 31, wid = tid >> 5;
    const int g = lane >> 2, tg = lane & 3;
    const int mb = (wid >> 1) * 32, nw = wid & 1;
    const int larow = lane & 15, lcol4 = (lane >> 4) * 4;
    const int brow = lane & 7, bcolo = ((lane >> 3) & 1) * 4;

    #pragma unroll
    for (int it = 0; it < 4; it++) {
        int idx = tid + it * 256;
        int r = idx >> 3, c4 = (idx & 7) * 4;
        const size_t gi = (size_t)(i0 + r) * 512 + gblk * 32 + c4;
        const size_t gj = (size_t)(j0 + r) * 512 + gblk * 32 + c4;
        *(uint4*)&Qh[r * 36 + c4] = *(const uint4*)&g_qh[gi];
        *(uint4*)&Ql[r * 36 + c4] = *(const uint4*)&g_ql[gi];
        *(uint4*)&Kh[r * 36 + c4] = *(const uint4*)&g_kh[gj];
        *(uint4*)&Kl[r * 36 + c4] = *(const uint4*)&g_kl[gj];
    }
    __syncthreads();

    float cs[2][8][4] = {};
    #pragma unroll
    for (int kt = 0; kt < 4; kt++) {
        const int kb = kt * 8;
        unsigned ah[2][4], al[2][4];
        #pragma unroll
        for (int mt = 0; mt < 2; mt++) {
            ldsm_x4(ah[mt][0], ah[mt][1], ah[mt][2], ah[mt][3],
                    sptr(&Qh[(mb + mt * 16 + larow) * 36 + kb + lcol4]));
            ldsm_x4(al[mt][0], al[mt][1], al[mt][2], al[mt][3],
                    sptr(&Ql[(mb + mt * 16 + larow) * 36 + kb + lcol4]));
        }
        #pragma unroll
        for (int nt = 0; nt < 8; nt++) {
            const int nb = nw * 64 + nt * 8;
            unsigned bh0, bh1, bl0, bl1;
            ldsm_x2(bh0, bh1, sptr(&Kh[(nb + brow) * 36 + kb + bcolo]));
            ldsm_x2(bl0, bl1, sptr(&Kl[(nb + brow) * 36 + kb + bcolo]));
            #pragma unroll
            for (int mt = 0; mt < 2; mt++) {
                float* c = cs[mt][nt];
                mma_bf16(c, ah[mt][0], ah[mt][1], ah[mt][2], ah[mt][3], bl0, bl1);
                mma_bf16(c, al[mt][0], al[mt][1], al[mt][2], al[mt][3], bh0, bh1);
                mma_bf16(c, ah[mt][0], ah[mt][1], ah[mt][2], ah[mt][3], bh0, bh1);
            }
        }
    }

    #pragma unroll
    for (int mt = 0; mt < 2; mt++) {
        #pragma unroll
        for (int nt = 0; nt < 8; nt++) {
            const int col = nw * 64 + nt * 8 + 2 * tg;
            const int r0 = mb + mt * 16 + g;
            float* p0 = &g_aff[(((size_t)(i0 + r0)) * 16 + gblk) * 1024 + j0 + col];
            float* p1 = &g_aff[(((size_t)(i0 + r0 + 8)) * 16 + gblk) * 1024 + j0 + col];
            float2 a0 = *(const float2*)p0;
            float2 a1 = *(const float2*)p1;
            *(float2*)p0 = make_float2(cs[mt][nt][0] * 0.125f * a0.x, cs[mt][nt][1] * 0.125f * a0.y);
            *(float2*)p1 = make_float2(cs[mt][nt][2] * 0.125f * a1.x, cs[mt][nt][3] * 0.125f * a1.y);
        }
    }
}

// ---------------------------------------------------------------------------
// K3b: online softmax over W + 3-pass bf16 P@V. 64-row i-tiles. (R12 version)
// ---------------------------------------------------------------------------
#define AT3_SMEM_U (4 * 2304 + 192)

__global__ void __launch_bounds__(256) k_attn2(
    const float* __restrict__ bout, float* __restrict__ out)
{
    extern __shared__ unsigned smau[];
    unsigned* Vh = smau;           // [j=64][36] (o-pairs)
    unsigned* Vl = Vh + 2304;
    unsigned* Ph = Vl + 2304;      // [i=64][36] (j-pairs)
    unsigned* Pl = Ph + 2304;
    float* m_s  = (float*)(Pl + 2304);   // [64]
    float* l_s  = m_s + 64;
    float* al_s = l_s + 64;

    const int gblk = blockIdx.y;
    const int i0 = blockIdx.x * 64;
    const int tid = threadIdx.x, lane = tid & 31, wid = tid >> 5;
    const int g = lane >> 2, tg = lane & 3;
    const int mb = (wid >> 1) * 16, nw = wid & 1;
    const int larow = lane & 15, lcol4 = (lane >> 4) * 4;

    if (tid < 64) { m_s[tid] = -1e30f; l_s[tid] = 0.f; }

    float co[4][4] = {};

    for (int c = 0; c < 16; c++) {
        const int j0 = c * 64;
        __syncthreads();

        #pragma unroll
        for (int it = 0; it < 2; it++) {
            int idx = tid + it * 256;
            int r = idx >> 3, c4 = (idx & 7) * 4;
            const size_t gv = (size_t)(j0 + r) * 512 + gblk * 32 + c4;
            *(uint4*)&Vh[r * 36 + c4] = *(const uint4*)&g_vh[gv];
            *(uint4*)&Vl[r * 36 + c4] = *(const uint4*)&g_vl[gv];
        }

        #pragma unroll
        for (int rr = 0; rr < 8; rr++) {
            const int row = wid * 8 + rr;
            float2 w2 = *(const float2*)&g_aff[(((size_t)(i0 + row)) * 16 + gblk) * 1024 + j0 + 2 * lane];
            float s0 = w2.x, s1 = w2.y;
            float mx = fmaxf(s0, s1);
            #pragma unroll
            for (int o = 16; o; o >>= 1) mx = fmaxf(mx, __shfl_xor_sync(0xffffffffu, mx, o));
            float mold = m_s[row];
            float mnew = fmaxf(mold, mx);
            float p0 = __expf(s0 - mnew), p1 = __expf(s1 - mnew);
            float su = p0 + p1;
            #pragma unroll
            for (int o = 16; o; o >>= 1) su += __shfl_xor_sync(0xffffffffu, su, o);
            if (lane == 0) {
                float alpha = __expf(mold - mnew);
                m_s[row] = mnew;
                al_s[row] = alpha;
                l_s[row] = l_s[row] * alpha + su;
            }
            unsigned ph, pl;
            pack2(p0, p1, ph, pl);
            Ph[row * 36 + lane] = ph;
            Pl[row * 36 + lane] = pl;
        }
        __syncthreads();

        {
            float a0 = al_s[mb + g], a1 = al_s[mb + g + 8];
            #pragma unroll
            for (int ont = 0; ont < 4; ont++) {
                co[ont][0] *= a0; co[ont][1] *= a0;
                co[ont][2] *= a1; co[ont][3] *= a1;
            }
            #pragma unroll
            for (int kt = 0; kt < 4; kt++) {
                const int kb = kt * 8;
                const int jb = kt * 16;
                unsigned ah[4], al[4];
                ldsm_x4(ah[0], ah[1], ah[2], ah[3], sptr(&Ph[(mb + larow) * 36 + kb + lcol4]));
                ldsm_x4(al[0], al[1], al[2], al[3], sptr(&Pl[(mb + larow) * 36 + kb + lcol4]));
                #pragma unroll
                for (int ont = 0; ont < 4; ont++) {
                    const int vcol = nw * 16 + ont * 4;
                    unsigned bh0, bh1, bl0, bl1;
                    ldsm_x2t(bh0, bh1, sptr(&Vh[(jb + larow) * 36 + vcol]));
                    ldsm_x2t(bl0, bl1, sptr(&Vl[(jb + larow) * 36 + vcol]));
                    mma_bf16(co[ont], ah[0], ah[1], ah[2], ah[3], bl0, bl1);
                    mma_bf16(co[ont], al[0], al[1], al[2], al[3], bh0, bh1);
                    mma_bf16(co[ont], ah[0], ah[1], ah[2], ah[3], bh0, bh1);
                }
            }
        }
    }
    __syncthreads();

    {
        float inv0 = 1.0f / l_s[mb + g];
        float inv1 = 1.0f / l_s[mb + g + 8];
        #pragma unroll
        for (int ont = 0; ont < 4; ont++) {
            const int cl = nw * 32 + ont * 8 + 2 * tg;
            const int col = gblk * 64 + cl;
            float b0 = bout[col], b1 = bout[col + 1];
            int r0 = i0 + mb + g;
            *(float2*)&out[(size_t)r0 * 1024 + col] =
                make_float2(co[ont][0] * inv0 + b0, co[ont][1] * inv0 + b1);
            *(float2*)&out[(size_t)(r0 + 8) * 1024 + col] =
                make_float2(co[ont][2] * inv1 + b0, co[ont][3] * inv1 + b1);
        }
    }
}

// ---------------------------------------------------------------------------
extern "C" void kernel_launch(void* const* d_in, const int* in_sizes, int n_in,
                              void* d_out, int out_size) {
    const float* roi  = (const float*)d_in[0];
    const float* pe   = (const float*)d_in[1];
    const float* W1   = (const float*)d_in[2];
    const float* b1   = (const float*)d_in[3];
    const float* W2   = (const float*)d_in[4];
    const float* b2   = (const float*)d_in[5];
    const float* Wq   = (const float*)d_in[6];
    const float* bq   = (const float*)d_in[7];
    const float* Wk   = (const float*)d_in[8];
    const float* bk   = (const float*)d_in[9];
    const float* Wout = (const float*)d_in[10];
    const float* bout = (const float*)d_in[11];
    float* out = (float*)d_out;

    const int g3_smem = (4 * K1_AS + 4 * K1_BS) * (int)sizeof(unsigned);
    const int pe_smem = (17408 + 4352 + 1088 + 64 + 16) * (int)sizeof(float);
    const int lg_smem = LGT_SMEM_U * (int)sizeof(unsigned);
    const int at_smem = AT3_SMEM_U * (int)sizeof(unsigned);
    cudaFuncSetAttribute(k_gemm3,  cudaFuncAttributeMaxDynamicSharedMemorySize, g3_smem);
    cudaFuncSetAttribute(k_pe,     cudaFuncAttributeMaxDynamicSharedMemorySize, pe_smem);
    cudaFuncSetAttribute(k_logits, cudaFuncAttributeMaxDynamicSharedMemorySize, lg_smem);
    cudaFuncSetAttribute(k_attn2,  cudaFuncAttributeMaxDynamicSharedMemorySize, at_smem);

    k_gemm3<<<dim3(8, 8, 3), 256, g3_smem>>>(roi, Wq, bq, Wk, bk, Wout);
    k_pe<<<(Nn * Nn) / 256, 256, pe_smem>>>(pe, W1, b1, W2, b2);
    k_logits<<<dim3(8, 8, 16), 256, lg_smem>>>();
    k_attn2<<<dim3(Nn / 64, Gg), 256, at_smem>>>(bout, out);
}

// round 14
// speedup vs baseline: 1.1730x; 1.1730x over previous
#include <cuda_runtime.h>
#include <cuda_bf16.h>
#include <math.h>

#define Nn 1024
#define Dd 1024
#define Gg 16

// Scratch (allocation-free rule: __device__ globals). Packed bf16 hi/lo pairs.
__device__ unsigned g_qh[Nn * 512], g_ql[Nn * 512];   // q [i][d/2]
__device__ unsigned g_kh[Nn * 512], g_kl[Nn * 512];   // k [j][d/2]
__device__ unsigned g_vh[Nn * 512], g_vl[Nn * 512];   // v2 [j][o/2]
__device__ float g_aff[(size_t)Nn * Gg * Nn];         // aff -> overwritten with weighted logits

__device__ __forceinline__ unsigned f2tf(float x) {
    unsigned u; asm("cvt.rna.tf32.f32 %0, %1;" : "=r"(u) : "f"(x)); return u;
}
__device__ __forceinline__ float ftanh(float x) {
    float y; asm("tanh.approx.f32 %0, %1;" : "=f"(y) : "f"(x)); return y;
}
__device__ __forceinline__ void mma_tf32(float* c,
    unsigned a0, unsigned a1, unsigned a2, unsigned a3,
    unsigned b0, unsigned b1) {
    asm volatile(
        "mma.sync.aligned.m16n8k8.row.col.f32.tf32.tf32.f32 "
        "{%0,%1,%2,%3}, {%4,%5,%6,%7}, {%8,%9}, {%0,%1,%2,%3};\n"
        : "+f"(c[0]), "+f"(c[1]), "+f"(c[2]), "+f"(c[3])
        : "r"(a0), "r"(a1), "r"(a2), "r"(a3), "r"(b0), "r"(b1));
}
__device__ __forceinline__ void mma_bf16(float* c,
    unsigned a0, unsigned a1, unsigned a2, unsigned a3,
    unsigned b0, unsigned b1) {
    asm volatile(
        "mma.sync.aligned.m16n8k16.row.col.f32.bf16.bf16.f32 "
        "{%0,%1,%2,%3}, {%4,%5,%6,%7}, {%8,%9}, {%0,%1,%2,%3};\n"
        : "+f"(c[0]), "+f"(c[1]), "+f"(c[2]), "+f"(c[3])
        : "r"(a0), "r"(a1), "r"(a2), "r"(a3), "r"(b0), "r"(b1));
}
__device__ __forceinline__ unsigned sptr(const void* p) {
    return (unsigned)__cvta_generic_to_shared(p);
}
__device__ __forceinline__ void ldsm_x4(unsigned& r0, unsigned& r1, unsigned& r2, unsigned& r3, unsigned a) {
    asm volatile("ldmatrix.sync.aligned.m8n8.x4.shared.b16 {%0,%1,%2,%3}, [%4];"
        : "=r"(r0), "=r"(r1), "=r"(r2), "=r"(r3) : "r"(a));
}
__device__ __forceinline__ void ldsm_x2(unsigned& r0, unsigned& r1, unsigned a) {
    asm volatile("ldmatrix.sync.aligned.m8n8.x2.shared.b16 {%0,%1}, [%2];"
        : "=r"(r0), "=r"(r1) : "r"(a));
}
__device__ __forceinline__ void ldsm_x2t(unsigned& r0, unsigned& r1, unsigned a) {
    asm volatile("ldmatrix.sync.aligned.m8n8.x2.trans.shared.b16 {%0,%1}, [%2];"
        : "=r"(r0), "=r"(r1) : "r"(a));
}
// bf16 hi/lo split of a pair (a->low half, b->high half)
__device__ __forceinline__ void pack2(float a, float b, unsigned& hi, unsigned& lo) {
    __nv_bfloat16 ba = __float2bfloat16(a), bb = __float2bfloat16(b);
    hi = ((unsigned)__bfloat16_as_ushort(bb) << 16) | (unsigned)__bfloat16_as_ushort(ba);
    __nv_bfloat16 la = __float2bfloat16(a - __bfloat162float(ba));
    __nv_bfloat16 lb = __float2bfloat16(b - __bfloat162float(bb));
    lo = ((unsigned)__bfloat16_as_ushort(lb) << 16) | (unsigned)__bfloat16_as_ushort(la);
}

// ---------------------------------------------------------------------------
// K1: three 1024^3 GEMMs via 3-pass bf16 mma (z=0: Q, z=1: K, z=2: V2)
// (R11 winner: LDG -> pack2 -> STS, double-buffered)
// ---------------------------------------------------------------------------
#define K1_AS 1536   // 128*12 b32 per A buffer
#define K1_BS 1088   // 16*68 b32 per B buffer

__global__ void __launch_bounds__(256, 2) k_gemm3(
    const float* __restrict__ roi,
    const float* __restrict__ Wq, const float* __restrict__ bq,
    const float* __restrict__ Wk, const float* __restrict__ bk,
    const float* __restrict__ Wout)
{
    extern __shared__ unsigned smu[];
    unsigned* Ah = smu;
    unsigned* Al = Ah + 2 * K1_AS;
    unsigned* Bh = Al + 2 * K1_AS;
    unsigned* Bl = Bh + 2 * K1_BS;

    const int z = blockIdx.z;
    const int rowBase = blockIdx.y * 128, colBase = blockIdx.x * 128;
    const int tid = threadIdx.x, lane = tid & 31, wid = tid >> 5;
    const int g = lane >> 2, tg = lane & 3;
    const int m_off = (wid >> 2) * 64, n_off = (wid & 3) * 32;
    const float* Bm = (z == 0) ? Wq : (z == 1) ? Wk : Wout;

    float acc[4][4][4] = {};
    const int larow = lane & 15, lcol4 = (lane >> 4) * 4;
    float4 aReg[2], bReg[2];

    {
        const int k0 = 0;
        #pragma unroll
        for (int it = 0; it < 2; it++) {
            int idx = tid + it * 256;
            int r = idx >> 2, c4 = idx & 3;
            aReg[it] = *(const float4*)&roi[(size_t)(rowBase + r) * 1024 + k0 + c4 * 4];
        }
        #pragma unroll
        for (int it = 0; it < 2; it++) {
            int idx = tid + it * 256;
            int kr = idx >> 5, c4 = idx & 31;
            int col = colBase + c4 * 4;
            const float* src;
            if (z < 2) src = &Bm[(size_t)(k0 + kr) * 1024 + col];
            else { int gg = col >> 6, oo = col & 63; src = &Bm[((size_t)gg * 1024 + (k0 + kr)) * 64 + oo]; }
            bReg[it] = *(const float4*)src;
        }
        #pragma unroll
        for (int it = 0; it < 2; it++) {
            int idx = tid + it * 256;
            int r = idx >> 2, c4 = idx & 3;
            unsigned h0, l0, h1, l1;
            pack2(aReg[it].x, aReg[it].y, h0, l0);
            pack2(aReg[it].z, aReg[it].w, h1, l1);
            Ah[r * 12 + c4 * 2] = h0; Ah[r * 12 + c4 * 2 + 1] = h1;
            Al[r * 12 + c4 * 2] = l0; Al[r * 12 + c4 * 2 + 1] = l1;
        }
        #pragma unroll
        for (int it = 0; it < 2; it++) {
            int idx = tid + it * 256;
            int kr = idx >> 5, c4 = idx & 31;
            unsigned h0, l0, h1, l1;
            pack2(bReg[it].x, bReg[it].y, h0, l0);
            pack2(bReg[it].z, bReg[it].w, h1, l1);
            Bh[kr * 68 + c4 * 2] = h0; Bh[kr * 68 + c4 * 2 + 1] = h1;
            Bl[kr * 68 + c4 * 2] = l0; Bl[kr * 68 + c4 * 2 + 1] = l1;
        }
    }
    __syncthreads();

    for (int s = 0; s < 64; s++) {
        const int buf = s & 1;
        if (s < 63) {
            const int k0 = (s + 1) * 16;
            #pragma unroll
            for (int it = 0; it < 2; it++) {
                int idx = tid + it * 256;
                int r = idx >> 2, c4 = idx & 3;
                aReg[it] = *(const float4*)&roi[(size_t)(rowBase + r) * 1024 + k0 + c4 * 4];
            }
            #pragma unroll
            for (int it = 0; it < 2; it++) {
                int idx = tid + it * 256;
                int kr = idx >> 5, c4 = idx & 31;
                int col = colBase + c4 * 4;
                const float* src;
                if (z < 2) src = &Bm[(size_t)(k0 + kr) * 1024 + col];
                else { int gg = col >> 6, oo = col & 63; src = &Bm[((size_t)gg * 1024 + (k0 + kr)) * 64 + oo]; }
                bReg[it] = *(const float4*)src;
            }
        }

        const unsigned* ah_b = Ah + buf * K1_AS;
        const unsigned* al_b = Al + buf * K1_AS;
        const unsigned* bh_b = Bh + buf * K1_BS;
        const unsigned* bl_b = Bl + buf * K1_BS;

        unsigned ah[4][4], al[4][4];
        #pragma unroll
        for (int mt = 0; mt < 4; mt++) {
            const int rb = m_off + mt * 16;
            ldsm_x4(ah[mt][0], ah[mt][1], ah[mt][2], ah[mt][3],
                    sptr(&ah_b[(rb + larow) * 12 + lcol4]));
            ldsm_x4(al[mt][0], al[mt][1], al[mt][2], al[mt][3],
                    sptr(&al_b[(rb + larow) * 12 + lcol4]));
        }
        #pragma unroll
        for (int nt = 0; nt < 4; nt++) {
            const int nbc = (n_off >> 1) + nt * 4;
            unsigned bh0, bh1, bl0, bl1;
            ldsm_x2t(bh0, bh1, sptr(&bh_b[larow * 68 + nbc]));
            ldsm_x2t(bl0, bl1, sptr(&bl_b[larow * 68 + nbc]));
            #pragma unroll
            for (int mt = 0; mt < 4; mt++) {
                mma_bf16(acc[mt][nt], ah[mt][0], ah[mt][1], ah[mt][2], ah[mt][3], bl0, bl1);
                mma_bf16(acc[mt][nt], al[mt][0], al[mt][1], al[mt][2], al[mt][3], bh0, bh1);
                mma_bf16(acc[mt][nt], ah[mt][0], ah[mt][1], ah[mt][2], ah[mt][3], bh0, bh1);
            }
        }

        if (s < 63) {
            unsigned* AhN = Ah + (buf ^ 1) * K1_AS;
            unsigned* AlN = Al + (buf ^ 1) * K1_AS;
            unsigned* BhN = Bh + (buf ^ 1) * K1_BS;
            unsigned* BlN = Bl + (buf ^ 1) * K1_BS;
            #pragma unroll
            for (int it = 0; it < 2; it++) {
                int idx = tid + it * 256;
                int r = idx >> 2, c4 = idx & 3;
                unsigned h0, l0, h1, l1;
                pack2(aReg[it].x, aReg[it].y, h0, l0);
                pack2(aReg[it].z, aReg[it].w, h1, l1);
                AhN[r * 12 + c4 * 2] = h0; AhN[r * 12 + c4 * 2 + 1] = h1;
                AlN[r * 12 + c4 * 2] = l0; AlN[r * 12 + c4 * 2 + 1] = l1;
            }
            #pragma unroll
            for (int it = 0; it < 2; it++) {
                int idx = tid + it * 256;
                int kr = idx >> 5, c4 = idx & 31;
                unsigned h0, l0, h1, l1;
                pack2(bReg[it].x, bReg[it].y, h0, l0);
                pack2(bReg[it].z, bReg[it].w, h1, l1);
                BhN[kr * 68 + c4 * 2] = h0; BhN[kr * 68 + c4 * 2 + 1] = h1;
                BlN[kr * 68 + c4 * 2] = l0; BlN[kr * 68 + c4 * 2 + 1] = l1;
            }
        }
        __syncthreads();
    }

    // epilogue: add bias, pack to bf16 hi/lo, store u32 pairs
    #pragma unroll
    for (int mt = 0; mt < 4; mt++) {
        #pragma unroll
        for (int nt = 0; nt < 4; nt++) {
            const int row = rowBase + m_off + mt * 16 + g;
            const int col = colBase + n_off + nt * 8 + 2 * tg;
            const size_t p0 = (size_t)row * 512 + (col >> 1);
            const size_t p1 = (size_t)(row + 8) * 512 + (col >> 1);
            float v0 = acc[mt][nt][0], v1 = acc[mt][nt][1];
            float v2 = acc[mt][nt][2], v3 = acc[mt][nt][3];
            unsigned h, l;
            if (z == 0) {
                float b0 = bq[col], b1 = bq[col + 1];
                pack2(v0 + b0, v1 + b1, h, l); g_qh[p0] = h; g_ql[p0] = l;
                pack2(v2 + b0, v3 + b1, h, l); g_qh[p1] = h; g_ql[p1] = l;
            } else if (z == 1) {
                float b0 = bk[col], b1 = bk[col + 1];
                pack2(v0 + b0, v1 + b1, h, l); g_kh[p0] = h; g_kl[p0] = l;
                pack2(v2 + b0, v3 + b1, h, l); g_kh[p1] = h; g_kl[p1] = l;
            } else {
                pack2(v0, v1, h, l); g_vh[p0] = h; g_vl[p0] = l;
                pack2(v2, v3, h, l); g_vh[p1] = h; g_vl[p1] = l;
            }
        }
    }
}

// ---------------------------------------------------------------------------
// K2: PE MLP. fc1 tf32 mma; tanh'ed h packed directly into bf16 A-fragments
// (fc1 C-layout == bf16 A-layout) -> fc2 bf16 3-pass, no H round-trip.
// ---------------------------------------------------------------------------
__global__ void __launch_bounds__(256, 2) k_pe(
    const float* __restrict__ pe,
    const float* __restrict__ W1, const float* __restrict__ b1,
    const float* __restrict__ W2, const float* __restrict__ b2)
{
    extern __shared__ float sm2[];
    float* H    = sm2;                     // 256*68
    float* W1sT = H + 17408;               // [n=64][k] stride 68
    unsigned* W2h = (unsigned*)(W1sT + 4352);  // [n=16][k-pairs] stride 36 = 576
    unsigned* W2l = W2h + 576;
    float* bb1  = (float*)(W2l + 576);     // 64
    float* bb2  = bb1 + 64;                // 16

    const int tid = threadIdx.x, lane = tid & 31, wid = tid >> 5;
    const int g = lane >> 2, tg = lane & 3;
    const int arow = lane & 15, acolo = (lane >> 4) * 4;
    const int brow = lane & 7, bcolo = ((lane >> 3) & 1) * 4;

    for (int l = tid; l < 4096; l += 256) {
        int k = l >> 6, n = l & 63;
        W1sT[n * 68 + k] = __uint_as_float(f2tf(W1[l]));
    }
    for (int l = tid; l < 512; l += 256) {     // 16 n x 32 k-pairs
        int n = l >> 5, kp = l & 31;
        float a = W2[(size_t)(2 * kp) * 16 + n];
        float b = W2[(size_t)(2 * kp + 1) * 16 + n];
        unsigned h, lo;
        pack2(a, b, h, lo);
        W2h[n * 36 + kp] = h; W2l[n * 36 + kp] = lo;
    }
    if (tid < 64) bb1[tid] = b1[tid];
    if (tid < 16) bb2[tid] = b2[tid];

    const size_t base = (size_t)blockIdx.x * 256 * 64;
    #pragma unroll
    for (int it = 0; it < 16; it++) {
        int idx = tid + it * 256;
        int r = idx >> 4, c4 = idx & 15;
        float4 v = *(const float4*)&pe[base + (size_t)idx * 4];
        float4 w;
        w.x = __uint_as_float(f2tf(v.x)); w.y = __uint_as_float(f2tf(v.y));
        w.z = __uint_as_float(f2tf(v.z)); w.w = __uint_as_float(f2tf(v.w));
        *(float4*)&H[r * 68 + c4 * 4] = w;
    }
    __syncthreads();

    const int rb0 = wid * 32;
    float acc[2][8][4] = {};
    #pragma unroll
    for (int kt = 0; kt < 8; kt++) {
        const int kb = kt * 8;
        unsigned a[2][4];
        #pragma unroll
        for (int mt = 0; mt < 2; mt++) {
            ldsm_x4(a[mt][0], a[mt][1], a[mt][2], a[mt][3],
                    sptr(&H[(rb0 + mt * 16 + arow) * 68 + kb + acolo]));
        }
        #pragma unroll
        for (int nt = 0; nt < 8; nt++) {
            unsigned b0, b1r;
            ldsm_x2(b0, b1r, sptr(&W1sT[(nt * 8 + brow) * 68 + kb + bcolo]));
            mma_tf32(acc[0][nt], a[0][0], a[0][1], a[0][2], a[0][3], b0, b1r);
            mma_tf32(acc[1][nt], a[1][0], a[1][1], a[1][2], a[1][3], b0, b1r);
        }
    }

    // tanh + pack directly into bf16 A-fragments (per mt,nt: rows g/g+8 pair)
    unsigned h01h[2][8], h01l[2][8], h23h[2][8], h23l[2][8];
    #pragma unroll
    for (int mt = 0; mt < 2; mt++) {
        #pragma unroll
        for (int nt = 0; nt < 8; nt++) {
            const int col = nt * 8 + 2 * tg;
            float h0 = ftanh(acc[mt][nt][0] + bb1[col]);
            float h1 = ftanh(acc[mt][nt][1] + bb1[col + 1]);
            float h2 = ftanh(acc[mt][nt][2] + bb1[col]);
            float h3 = ftanh(acc[mt][nt][3] + bb1[col + 1]);
            pack2(h0, h1, h01h[mt][nt], h01l[mt][nt]);
            pack2(h2, h3, h23h[mt][nt], h23l[mt][nt]);
        }
    }

    // fc2: bf16 3-pass, A-fragments from registers
    float acc2[2][2][4] = {};
    #pragma unroll
    for (int kt = 0; kt < 4; kt++) {
        const int kb = kt * 8;   // k-pair offset
        #pragma unroll
        for (int ntb = 0; ntb < 2; ntb++) {
            unsigned bh0, bh1, bl0, bl1;
            ldsm_x2(bh0, bh1, sptr(&W2h[(ntb * 8 + brow) * 36 + kb + bcolo]));
            ldsm_x2(bl0, bl1, sptr(&W2l[(ntb * 8 + brow) * 36 + kb + bcolo]));
            #pragma unroll
            for (int mt = 0; mt < 2; mt++) {
                unsigned a0 = h01h[mt][2 * kt],     a1 = h23h[mt][2 * kt];
                unsigned a2 = h01h[mt][2 * kt + 1], a3 = h23h[mt][2 * kt + 1];
                unsigned c0 = h01l[mt][2 * kt],     c1 = h23l[mt][2 * kt];
                unsigned c2 = h01l[mt][2 * kt + 1], c3 = h23l[mt][2 * kt + 1];
                mma_bf16(acc2[mt][ntb], a0, a1, a2, a3, bl0, bl1);
                mma_bf16(acc2[mt][ntb], c0, c1, c2, c3, bh0, bh1);
                mma_bf16(acc2[mt][ntb], a0, a1, a2, a3, bh0, bh1);
            }
        }
    }

    const int growBase = blockIdx.x * 256;
    const int i = growBase >> 10;
    #pragma unroll
    for (int mt = 0; mt < 2; mt++) {
        #pragma unroll
        for (int nt = 0; nt < 2; nt++) {
            #pragma unroll
            for (int e = 0; e < 4; e++) {
                int grow = growBase + rb0 + mt * 16 + g + ((e >= 2) ? 8 : 0);
                int j = grow & 1023;
                int col = nt * 8 + 2 * tg + (e & 1);
                g_aff[((size_t)i * 16 + col) * 1024 + j] = acc2[mt][nt][e] + bb2[col];
            }
        }
    }
}

// ---------------------------------------------------------------------------
// K3a: weighted logits W = aff * (Q K^T / 8) in place. 64x64 tiles (R11).
// ---------------------------------------------------------------------------
#define LGT_SMEM_U (4 * 2304)

__global__ void __launch_bounds__(256) k_logits()
{
    extern __shared__ unsigned smlu[];
    unsigned* Qh = smlu;          // [64][36]
    unsigned* Ql = Qh + 2304;
    unsigned* Kh = Ql + 2304;
    unsigned* Kl = Kh + 2304;

    const int gblk = blockIdx.z;
    const int i0 = blockIdx.y * 64, j0 = blockIdx.x * 64;
    const int tid = threadIdx.x, lane = tid & 31, wid = tid >> 5;
    const int g = lane >> 2, tg = lane & 3;
    const int mb = (wid >> 1) * 16, nw = wid & 1;
    const int larow = lane & 15, lcol4 = (lane >> 4) * 4;
    const int brow = lane & 7, bcolo = ((lane >> 3) & 1) * 4;

    #pragma unroll
    for (int it = 0; it < 2; it++) {
        int idx = tid + it * 256;
        int r = idx >> 3, c4 = (idx & 7) * 4;
        const size_t gi = (size_t)(i0 + r) * 512 + gblk * 32 + c4;
        const size_t gj = (size_t)(j0 + r) * 512 + gblk * 32 + c4;
        *(uint4*)&Qh[r * 36 + c4] = *(const uint4*)&g_qh[gi];
        *(uint4*)&Ql[r * 36 + c4] = *(const uint4*)&g_ql[gi];
        *(uint4*)&Kh[r * 36 + c4] = *(const uint4*)&g_kh[gj];
        *(uint4*)&Kl[r * 36 + c4] = *(const uint4*)&g_kl[gj];
    }
    __syncthreads();

    float cs[4][4] = {};
    #pragma unroll
    for (int kt = 0; kt < 4; kt++) {
        const int kb = kt * 8;
        unsigned ah[4], al[4];
        ldsm_x4(ah[0], ah[1], ah[2], ah[3], sptr(&Qh[(mb + larow) * 36 + kb + lcol4]));
        ldsm_x4(al[0], al[1], al[2], al[3], sptr(&Ql[(mb + larow) * 36 + kb + lcol4]));
        #pragma unroll
        for (int nt = 0; nt < 4; nt++) {
            const int nb = nw * 32 + nt * 8;
            unsigned bh0, bh1, bl0, bl1;
            ldsm_x2(bh0, bh1, sptr(&Kh[(nb + brow) * 36 + kb + bcolo]));
            ldsm_x2(bl0, bl1, sptr(&Kl[(nb + brow) * 36 + kb + bcolo]));
            mma_bf16(cs[nt], ah[0], ah[1], ah[2], ah[3], bl0, bl1);
            mma_bf16(cs[nt], al[0], al[1], al[2], al[3], bh0, bh1);
            mma_bf16(cs[nt], ah[0], ah[1], ah[2], ah[3], bh0, bh1);
        }
    }

    #pragma unroll
    for (int nt = 0; nt < 4; nt++) {
        const int col = nw * 32 + nt * 8 + 2 * tg;
        const int r0 = mb + g;
        float* p0 = &g_aff[(((size_t)(i0 + r0)) * 16 + gblk) * 1024 + j0 + col];
        float* p1 = &g_aff[(((size_t)(i0 + r0 + 8)) * 16 + gblk) * 1024 + j0 + col];
        float2 a0 = *(const float2*)p0;
        float2 a1 = *(const float2*)p1;
        *(float2*)p0 = make_float2(cs[nt][0] * 0.125f * a0.x, cs[nt][1] * 0.125f * a0.y);
        *(float2*)p1 = make_float2(cs[nt][2] * 0.125f * a1.x, cs[nt][3] * 0.125f * a1.y);
    }
}

// ---------------------------------------------------------------------------
// K3b: online softmax over W + 3-pass bf16 P@V. 32-row i-tiles (R11 winner).
// ---------------------------------------------------------------------------
#define AT2_SMEM_U (2 * 2304 + 2 * 1152 + 96)

__global__ void __launch_bounds__(256) k_attn2(
    const float* __restrict__ bout, float* __restrict__ out)
{
    extern __shared__ unsigned smau[];
    unsigned* Vh = smau;           // [j=64][36] (o-pairs)
    unsigned* Vl = Vh + 2304;
    unsigned* Ph = Vl + 2304;      // [i=32][36] (j-pairs)
    unsigned* Pl = Ph + 1152;
    float* m_s  = (float*)(Pl + 1152);   // [32]
    float* l_s  = m_s + 32;
    float* al_s = l_s + 32;

    const int gblk = blockIdx.y;
    const int i0 = blockIdx.x * 32;
    const int tid = threadIdx.x, lane = tid & 31, wid = tid >> 5;
    const int g = lane >> 2, tg = lane & 3;
    const int mb = (wid >> 2) * 16, nw = wid & 3;
    const int larow = lane & 15, lcol4 = (lane >> 4) * 4;

    if (tid < 32) { m_s[tid] = -1e30f; l_s[tid] = 0.f; }

    float co[2][4] = {};

    for (int c = 0; c < 16; c++) {
        const int j0 = c * 64;
        __syncthreads();

        #pragma unroll
        for (int it = 0; it < 2; it++) {
            int idx = tid + it * 256;
            int r = idx >> 3, c4 = (idx & 7) * 4;
            const size_t gv = (size_t)(j0 + r) * 512 + gblk * 32 + c4;
            *(uint4*)&Vh[r * 36 + c4] = *(const uint4*)&g_vh[gv];
            *(uint4*)&Vl[r * 36 + c4] = *(const uint4*)&g_vl[gv];
        }

        #pragma unroll
        for (int rr = 0; rr < 4; rr++) {
            const int row = wid * 4 + rr;
            float2 w2 = *(const float2*)&g_aff[(((size_t)(i0 + row)) * 16 + gblk) * 1024 + j0 + 2 * lane];
            float s0 = w2.x, s1 = w2.y;
            float mx = fmaxf(s0, s1);
            #pragma unroll
            for (int o = 16; o; o >>= 1) mx = fmaxf(mx, __shfl_xor_sync(0xffffffffu, mx, o));
            float mold = m_s[row];
            float mnew = fmaxf(mold, mx);
            float p0 = __expf(s0 - mnew), p1 = __expf(s1 - mnew);
            float su = p0 + p1;
            #pragma unroll
            for (int o = 16; o; o >>= 1) su += __shfl_xor_sync(0xffffffffu, su, o);
            if (lane == 0) {
                float alpha = __expf(mold - mnew);
                m_s[row] = mnew;
                al_s[row] = alpha;
                l_s[row] = l_s[row] * alpha + su;
            }
            unsigned ph, pl;
            pack2(p0, p1, ph, pl);
            Ph[row * 36 + lane] = ph;
            Pl[row * 36 + lane] = pl;
        }
        __syncthreads();

        {
            float a0 = al_s[mb + g], a1 = al_s[mb + g + 8];
            #pragma unroll
            for (int nt = 0; nt < 2; nt++) {
                co[nt][0] *= a0; co[nt][1] *= a0;
                co[nt][2] *= a1; co[nt][3] *= a1;
            }
            #pragma unroll
            for (int kt = 0; kt < 4; kt++) {
                const int kb = kt * 8;        // j-pair offset for P
                const int jb = kt * 16;       // j-row offset for V
                unsigned ah[4], al[4];
                ldsm_x4(ah[0], ah[1], ah[2], ah[3], sptr(&Ph[(mb + larow) * 36 + kb + lcol4]));
                ldsm_x4(al[0], al[1], al[2], al[3], sptr(&Pl[(mb + larow) * 36 + kb + lcol4]));
                #pragma unroll
                for (int nt = 0; nt < 2; nt++) {
                    const int vcol = nw * 8 + nt * 4;   // o-pair column
                    unsigned bh0, bh1, bl0, bl1;
                    ldsm_x2t(bh0, bh1, sptr(&Vh[(jb + larow) * 36 + vcol]));
                    ldsm_x2t(bl0, bl1, sptr(&Vl[(jb + larow) * 36 + vcol]));
                    mma_bf16(co[nt], ah[0], ah[1], ah[2], ah[3], bl0, bl1);
                    mma_bf16(co[nt], al[0], al[1], al[2], al[3], bh0, bh1);
                    mma_bf16(co[nt], ah[0], ah[1], ah[2], ah[3], bh0, bh1);
                }
            }
        }
    }
    __syncthreads();

    {
        float inv0 = 1.0f / l_s[mb + g];
        float inv1 = 1.0f / l_s[mb + g + 8];
        #pragma unroll
        for (int nt = 0; nt < 2; nt++) {
            const int cl = nw * 16 + nt * 8 + 2 * tg;
            const int col = gblk * 64 + cl;
            float b0 = bout[col], b1 = bout[col + 1];
            int r0 = i0 + mb + g;
            *(float2*)&out[(size_t)r0 * 1024 + col] =
                make_float2(co[nt][0] * inv0 + b0, co[nt][1] * inv0 + b1);
            *(float2*)&out[(size_t)(r0 + 8) * 1024 + col] =
                make_float2(co[nt][2] * inv1 + b0, co[nt][3] * inv1 + b1);
        }
    }
}

// ---------------------------------------------------------------------------
extern "C" void kernel_launch(void* const* d_in, const int* in_sizes, int n_in,
                              void* d_out, int out_size) {
    const float* roi  = (const float*)d_in[0];
    const float* pe   = (const float*)d_in[1];
    const float* W1   = (const float*)d_in[2];
    const float* b1   = (const float*)d_in[3];
    const float* W2   = (const float*)d_in[4];
    const float* b2   = (const float*)d_in[5];
    const float* Wq   = (const float*)d_in[6];
    const float* bq   = (const float*)d_in[7];
    const float* Wk   = (const float*)d_in[8];
    const float* bk   = (const float*)d_in[9];
    const float* Wout = (const float*)d_in[10];
    const float* bout = (const float*)d_in[11];
    float* out = (float*)d_out;

    const int g3_smem = (4 * K1_AS + 4 * K1_BS) * (int)sizeof(unsigned);
    const int pe_smem = (17408 + 4352 + 80) * (int)sizeof(float) + 1152 * (int)sizeof(unsigned);
    const int lg_smem = LGT_SMEM_U * (int)sizeof(unsigned);
    const int at_smem = AT2_SMEM_U * (int)sizeof(unsigned);
    cudaFuncSetAttribute(k_gemm3,  cudaFuncAttributeMaxDynamicSharedMemorySize, g3_smem);
    cudaFuncSetAttribute(k_pe,     cudaFuncAttributeMaxDynamicSharedMemorySize, pe_smem);
    cudaFuncSetAttribute(k_logits, cudaFuncAttributeMaxDynamicSharedMemorySize, lg_smem);
    cudaFuncSetAttribute(k_attn2,  cudaFuncAttributeMaxDynamicSharedMemorySize, at_smem);

    k_gemm3<<<dim3(8, 8, 3), 256, g3_smem>>>(roi, Wq, bq, Wk, bk, Wout);
    k_pe<<<(Nn * Nn) / 256, 256, pe_smem>>>(pe, W1, b1, W2, b2);
    k_logits<<<dim3(16, 16, 16), 256, lg_smem>>>();
    k_attn2<<<dim3(Nn / 32, Gg), 256, at_smem>>>(bout, out);
}

// round 16
// speedup vs baseline: 1.2033x; 1.0259x over previous
#include <cuda_runtime.h>
#include <cuda_bf16.h>
#include <math.h>

#define Nn 1024
#define Dd 1024
#define Gg 16

// Scratch (allocation-free rule: __device__ globals). Packed bf16 hi/lo pairs.
__device__ unsigned g_qh[Nn * 512], g_ql[Nn * 512];   // q [i][d/2]
__device__ unsigned g_kh[Nn * 512], g_kl[Nn * 512];   // k [j][d/2]
__device__ unsigned g_vh[Nn * 512], g_vl[Nn * 512];   // v2 [j][o/2]
__device__ float g_aff[(size_t)Nn * Gg * Nn];         // aff -> overwritten with weighted logits

__device__ __forceinline__ unsigned f2tf(float x) {
    unsigned u; asm("cvt.rna.tf32.f32 %0, %1;" : "=r"(u) : "f"(x)); return u;
}
__device__ __forceinline__ unsigned u2tf(unsigned x) {
    unsigned u; asm("cvt.rna.tf32.f32 %0, %1;" : "=r"(u) : "f"(__uint_as_float(x))); return u;
}
__device__ __forceinline__ float ftanh(float x) {
    float y; asm("tanh.approx.f32 %0, %1;" : "=f"(y) : "f"(x)); return y;
}
__device__ __forceinline__ void mma_tf32(float* c,
    unsigned a0, unsigned a1, unsigned a2, unsigned a3,
    unsigned b0, unsigned b1) {
    asm volatile(
        "mma.sync.aligned.m16n8k8.row.col.f32.tf32.tf32.f32 "
        "{%0,%1,%2,%3}, {%4,%5,%6,%7}, {%8,%9}, {%0,%1,%2,%3};\n"
        : "+f"(c[0]), "+f"(c[1]), "+f"(c[2]), "+f"(c[3])
        : "r"(a0), "r"(a1), "r"(a2), "r"(a3), "r"(b0), "r"(b1));
}
__device__ __forceinline__ void mma_bf16(float* c,
    unsigned a0, unsigned a1, unsigned a2, unsigned a3,
    unsigned b0, unsigned b1) {
    asm volatile(
        "mma.sync.aligned.m16n8k16.row.col.f32.bf16.bf16.f32 "
        "{%0,%1,%2,%3}, {%4,%5,%6,%7}, {%8,%9}, {%0,%1,%2,%3};\n"
        : "+f"(c[0]), "+f"(c[1]), "+f"(c[2]), "+f"(c[3])
        : "r"(a0), "r"(a1), "r"(a2), "r"(a3), "r"(b0), "r"(b1));
}
__device__ __forceinline__ unsigned sptr(const void* p) {
    return (unsigned)__cvta_generic_to_shared(p);
}
__device__ __forceinline__ void ldsm_x4(unsigned& r0, unsigned& r1, unsigned& r2, unsigned& r3, unsigned a) {
    asm volatile("ldmatrix.sync.aligned.m8n8.x4.shared.b16 {%0,%1,%2,%3}, [%4];"
        : "=r"(r0), "=r"(r1), "=r"(r2), "=r"(r3) : "r"(a));
}
__device__ __forceinline__ void ldsm_x2(unsigned& r0, unsigned& r1, unsigned a) {
    asm volatile("ldmatrix.sync.aligned.m8n8.x2.shared.b16 {%0,%1}, [%2];"
        : "=r"(r0), "=r"(r1) : "r"(a));
}
__device__ __forceinline__ void ldsm_x2t(unsigned& r0, unsigned& r1, unsigned a) {
    asm volatile("ldmatrix.sync.aligned.m8n8.x2.trans.shared.b16 {%0,%1}, [%2];"
        : "=r"(r0), "=r"(r1) : "r"(a));
}
__device__ __forceinline__ void cpa16(unsigned dst, const void* src) {
    asm volatile("cp.async.ca.shared.global [%0], [%1], 16;" :: "r"(dst), "l"(src));
}
#define CP_COMMIT asm volatile("cp.async.commit_group;")
#define CP_WAIT0  asm volatile("cp.async.wait_group 0;")

// bf16 hi/lo split of a pair (a->low half, b->high half)
__device__ __forceinline__ void pack2(float a, float b, unsigned& hi, unsigned& lo) {
    __nv_bfloat16 ba = __float2bfloat16(a), bb = __float2bfloat16(b);
    hi = ((unsigned)__bfloat16_as_ushort(bb) << 16) | (unsigned)__bfloat16_as_ushort(ba);
    __nv_bfloat16 la = __float2bfloat16(a - __bfloat162float(ba));
    __nv_bfloat16 lb = __float2bfloat16(b - __bfloat162float(bb));
    lo = ((unsigned)__bfloat16_as_ushort(lb) << 16) | (unsigned)__bfloat16_as_ushort(la);
}

// ---------------------------------------------------------------------------
// K1: three 1024^3 GEMMs via 3-pass bf16 mma (z=0: Q, z=1: K, z=2: V2)
// (R11 winner, unchanged)
// ---------------------------------------------------------------------------
#define K1_AS 1536   // 128*12 b32 per A buffer
#define K1_BS 1088   // 16*68 b32 per B buffer

__global__ void __launch_bounds__(256, 2) k_gemm3(
    const float* __restrict__ roi,
    const float* __restrict__ Wq, const float* __restrict__ bq,
    const float* __restrict__ Wk, const float* __restrict__ bk,
    const float* __restrict__ Wout)
{
    extern __shared__ unsigned smu[];
    unsigned* Ah = smu;
    unsigned* Al = Ah + 2 * K1_AS;
    unsigned* Bh = Al + 2 * K1_AS;
    unsigned* Bl = Bh + 2 * K1_BS;

    const int z = blockIdx.z;
    const int rowBase = blockIdx.y * 128, colBase = blockIdx.x * 128;
    const int tid = threadIdx.x, lane = tid & 31, wid = tid >> 5;
    const int g = lane >> 2, tg = lane & 3;
    const int m_off = (wid >> 2) * 64, n_off = (wid & 3) * 32;
    const float* Bm = (z == 0) ? Wq : (z == 1) ? Wk : Wout;

    float acc[4][4][4] = {};
    const int larow = lane & 15, lcol4 = (lane >> 4) * 4;
    float4 aReg[2], bReg[2];

    {
        const int k0 = 0;
        #pragma unroll
        for (int it = 0; it < 2; it++) {
            int idx = tid + it * 256;
            int r = idx >> 2, c4 = idx & 3;
            aReg[it] = *(const float4*)&roi[(size_t)(rowBase + r) * 1024 + k0 + c4 * 4];
        }
        #pragma unroll
        for (int it = 0; it < 2; it++) {
            int idx = tid + it * 256;
            int kr = idx >> 5, c4 = idx & 31;
            int col = colBase + c4 * 4;
            const float* src;
            if (z < 2) src = &Bm[(size_t)(k0 + kr) * 1024 + col];
            else { int gg = col >> 6, oo = col & 63; src = &Bm[((size_t)gg * 1024 + (k0 + kr)) * 64 + oo]; }
            bReg[it] = *(const float4*)src;
        }
        #pragma unroll
        for (int it = 0; it < 2; it++) {
            int idx = tid + it * 256;
            int r = idx >> 2, c4 = idx & 3;
            unsigned h0, l0, h1, l1;
            pack2(aReg[it].x, aReg[it].y, h0, l0);
            pack2(aReg[it].z, aReg[it].w, h1, l1);
            Ah[r * 12 + c4 * 2] = h0; Ah[r * 12 + c4 * 2 + 1] = h1;
            Al[r * 12 + c4 * 2] = l0; Al[r * 12 + c4 * 2 + 1] = l1;
        }
        #pragma unroll
        for (int it = 0; it < 2; it++) {
            int idx = tid + it * 256;
            int kr = idx >> 5, c4 = idx & 31;
            unsigned h0, l0, h1, l1;
            pack2(bReg[it].x, bReg[it].y, h0, l0);
            pack2(bReg[it].z, bReg[it].w, h1, l1);
            Bh[kr * 68 + c4 * 2] = h0; Bh[kr * 68 + c4 * 2 + 1] = h1;
            Bl[kr * 68 + c4 * 2] = l0; Bl[kr * 68 + c4 * 2 + 1] = l1;
        }
    }
    __syncthreads();

    for (int s = 0; s < 64; s++) {
        const int buf = s & 1;
        if (s < 63) {
            const int k0 = (s + 1) * 16;
            #pragma unroll
            for (int it = 0; it < 2; it++) {
                int idx = tid + it * 256;
                int r = idx >> 2, c4 = idx & 3;
                aReg[it] = *(const float4*)&roi[(size_t)(rowBase + r) * 1024 + k0 + c4 * 4];
            }
            #pragma unroll
            for (int it = 0; it < 2; it++) {
                int idx = tid + it * 256;
                int kr = idx >> 5, c4 = idx & 31;
                int col = colBase + c4 * 4;
                const float* src;
                if (z < 2) src = &Bm[(size_t)(k0 + kr) * 1024 + col];
                else { int gg = col >> 6, oo = col & 63; src = &Bm[((size_t)gg * 1024 + (k0 + kr)) * 64 + oo]; }
                bReg[it] = *(const float4*)src;
            }
        }

        const unsigned* ah_b = Ah + buf * K1_AS;
        const unsigned* al_b = Al + buf * K1_AS;
        const unsigned* bh_b = Bh + buf * K1_BS;
        const unsigned* bl_b = Bl + buf * K1_BS;

        unsigned ah[4][4], al[4][4];
        #pragma unroll
        for (int mt = 0; mt < 4; mt++) {
            const int rb = m_off + mt * 16;
            ldsm_x4(ah[mt][0], ah[mt][1], ah[mt][2], ah[mt][3],
                    sptr(&ah_b[(rb + larow) * 12 + lcol4]));
            ldsm_x4(al[mt][0], al[mt][1], al[mt][2], al[mt][3],
                    sptr(&al_b[(rb + larow) * 12 + lcol4]));
        }
        #pragma unroll
        for (int nt = 0; nt < 4; nt++) {
            const int nbc = (n_off >> 1) + nt * 4;
            unsigned bh0, bh1, bl0, bl1;
            ldsm_x2t(bh0, bh1, sptr(&bh_b[larow * 68 + nbc]));
            ldsm_x2t(bl0, bl1, sptr(&bl_b[larow * 68 + nbc]));
            #pragma unroll
            for (int mt = 0; mt < 4; mt++) {
                mma_bf16(acc[mt][nt], ah[mt][0], ah[mt][1], ah[mt][2], ah[mt][3], bl0, bl1);
                mma_bf16(acc[mt][nt], al[mt][0], al[mt][1], al[mt][2], al[mt][3], bh0, bh1);
                mma_bf16(acc[mt][nt], ah[mt][0], ah[mt][1], ah[mt][2], ah[mt][3], bh0, bh1);
            }
        }

        if (s < 63) {
            unsigned* AhN = Ah + (buf ^ 1) * K1_AS;
            unsigned* AlN = Al + (buf ^ 1) * K1_AS;
            unsigned* BhN = Bh + (buf ^ 1) * K1_BS;
            unsigned* BlN = Bl + (buf ^ 1) * K1_BS;
            #pragma unroll
            for (int it = 0; it < 2; it++) {
                int idx = tid + it * 256;
                int r = idx >> 2, c4 = idx & 3;
                unsigned h0, l0, h1, l1;
                pack2(aReg[it].x, aReg[it].y, h0, l0);
                pack2(aReg[it].z, aReg[it].w, h1, l1);
                AhN[r * 12 + c4 * 2] = h0; AhN[r * 12 + c4 * 2 + 1] = h1;
                AlN[r * 12 + c4 * 2] = l0; AlN[r * 12 + c4 * 2 + 1] = l1;
            }
            #pragma unroll
            for (int it = 0; it < 2; it++) {
                int idx = tid + it * 256;
                int kr = idx >> 5, c4 = idx & 31;
                unsigned h0, l0, h1, l1;
                pack2(bReg[it].x, bReg[it].y, h0, l0);
                pack2(bReg[it].z, bReg[it].w, h1, l1);
                BhN[kr * 68 + c4 * 2] = h0; BhN[kr * 68 + c4 * 2 + 1] = h1;
                BlN[kr * 68 + c4 * 2] = l0; BlN[kr * 68 + c4 * 2 + 1] = l1;
            }
        }
        __syncthreads();
    }

    // epilogue: add bias, pack to bf16 hi/lo, store u32 pairs
    #pragma unroll
    for (int mt = 0; mt < 4; mt++) {
        #pragma unroll
        for (int nt = 0; nt < 4; nt++) {
            const int row = rowBase + m_off + mt * 16 + g;
            const int col = colBase + n_off + nt * 8 + 2 * tg;
            const size_t p0 = (size_t)row * 512 + (col >> 1);
            const size_t p1 = (size_t)(row + 8) * 512 + (col >> 1);
            float v0 = acc[mt][nt][0], v1 = acc[mt][nt][1];
            float v2 = acc[mt][nt][2], v3 = acc[mt][nt][3];
            unsigned h, l;
            if (z == 0) {
                float b0 = bq[col], b1 = bq[col + 1];
                pack2(v0 + b0, v1 + b1, h, l); g_qh[p0] = h; g_ql[p0] = l;
                pack2(v2 + b0, v3 + b1, h, l); g_qh[p1] = h; g_ql[p1] = l;
            } else if (z == 1) {
                float b0 = bk[col], b1 = bk[col + 1];
                pack2(v0 + b0, v1 + b1, h, l); g_kh[p0] = h; g_kl[p0] = l;
                pack2(v2 + b0, v3 + b1, h, l); g_kh[p1] = h; g_kl[p1] = l;
            } else {
                pack2(v0, v1, h, l); g_vh[p0] = h; g_vl[p0] = l;
                pack2(v2, v3, h, l); g_vh[p1] = h; g_vl[p1] = l;
            }
        }
    }
}

// ---------------------------------------------------------------------------
// K2: PE MLP. pe staged via cp.async (raw fp32); cvt.rna applied on fragment
// regs after ldmatrix. fc1 tf32; fc2 bf16 3-pass from registers (R14).
// ---------------------------------------------------------------------------
__global__ void __launch_bounds__(256, 2) k_pe(
    const float* __restrict__ pe,
    const float* __restrict__ W1, const float* __restrict__ b1,
    const float* __restrict__ W2, const float* __restrict__ b2)
{
    extern __shared__ float sm2[];
    float* H    = sm2;                     // 256*68 (raw fp32 pe tile)
    float* W1sT = H + 17408;               // [n=64][k] stride 68
    unsigned* W2h = (unsigned*)(W1sT + 4352);  // [n=16][k-pairs] stride 36 = 576
    unsigned* W2l = W2h + 576;
    float* bb1  = (float*)(W2l + 576);     // 64
    float* bb2  = bb1 + 64;                // 16

    const int tid = threadIdx.x, lane = tid & 31, wid = tid >> 5;
    const int g = lane >> 2, tg = lane & 3;
    const int arow = lane & 15, acolo = (lane >> 4) * 4;
    const int brow = lane & 7, bcolo = ((lane >> 3) & 1) * 4;

    // pe tile: pure cp.async staging (no register round-trip, no cvt)
    const size_t base = (size_t)blockIdx.x * 256 * 64;
    #pragma unroll
    for (int it = 0; it < 16; it++) {
        int idx = tid + it * 256;
        int r = idx >> 4, c4 = idx & 15;
        cpa16(sptr(&H[r * 68 + c4 * 4]), &pe[base + (size_t)idx * 4]);
    }
    CP_COMMIT;

    for (int l = tid; l < 4096; l += 256) {
        int k = l >> 6, n = l & 63;
        W1sT[n * 68 + k] = __uint_as_float(f2tf(W1[l]));
    }
    for (int l = tid; l < 512; l += 256) {     // 16 n x 32 k-pairs
        int n = l >> 5, kp = l & 31;
        float a = W2[(size_t)(2 * kp) * 16 + n];
        float b = W2[(size_t)(2 * kp + 1) * 16 + n];
        unsigned h, lo;
        pack2(a, b, h, lo);
        W2h[n * 36 + kp] = h; W2l[n * 36 + kp] = lo;
    }
    if (tid < 64) bb1[tid] = b1[tid];
    if (tid < 16) bb2[tid] = b2[tid];

    CP_WAIT0;
    __syncthreads();

    const int rb0 = wid * 32;
    float acc[2][8][4] = {};
    #pragma unroll
    for (int kt = 0; kt < 8; kt++) {
        const int kb = kt * 8;
        unsigned a[2][4];
        #pragma unroll
        for (int mt = 0; mt < 2; mt++) {
            ldsm_x4(a[mt][0], a[mt][1], a[mt][2], a[mt][3],
                    sptr(&H[(rb0 + mt * 16 + arow) * 68 + kb + acolo]));
            a[mt][0] = u2tf(a[mt][0]); a[mt][1] = u2tf(a[mt][1]);
            a[mt][2] = u2tf(a[mt][2]); a[mt][3] = u2tf(a[mt][3]);
        }
        #pragma unroll
        for (int nt = 0; nt < 8; nt++) {
            unsigned b0, b1r;
            ldsm_x2(b0, b1r, sptr(&W1sT[(nt * 8 + brow) * 68 + kb + bcolo]));
            mma_tf32(acc[0][nt], a[0][0], a[0][1], a[0][2], a[0][3], b0, b1r);
            mma_tf32(acc[1][nt], a[1][0], a[1][1], a[1][2], a[1][3], b0, b1r);
        }
    }

    // tanh + pack directly into bf16 A-fragments
    unsigned h01h[2][8], h01l[2][8], h23h[2][8], h23l[2][8];
    #pragma unroll
    for (int mt = 0; mt < 2; mt++) {
        #pragma unroll
        for (int nt = 0; nt < 8; nt++) {
            const int col = nt * 8 + 2 * tg;
            float h0 = ftanh(acc[mt][nt][0] + bb1[col]);
            float h1 = ftanh(acc[mt][nt][1] + bb1[col + 1]);
            float h2 = ftanh(acc[mt][nt][2] + bb1[col]);
            float h3 = ftanh(acc[mt][nt][3] + bb1[col + 1]);
            pack2(h0, h1, h01h[mt][nt], h01l[mt][nt]);
            pack2(h2, h3, h23h[mt][nt], h23l[mt][nt]);
        }
    }

    // fc2: bf16 3-pass, A-fragments from registers
    float acc2[2][2][4] = {};
    #pragma unroll
    for (int kt = 0; kt < 4; kt++) {
        const int kb = kt * 8;   // k-pair offset
        #pragma unroll
        for (int ntb = 0; ntb < 2; ntb++) {
            unsigned bh0, bh1, bl0, bl1;
            ldsm_x2(bh0, bh1, sptr(&W2h[(ntb * 8 + brow) * 36 + kb + bcolo]));
            ldsm_x2(bl0, bl1, sptr(&W2l[(ntb * 8 + brow) * 36 + kb + bcolo]));
            #pragma unroll
            for (int mt = 0; mt < 2; mt++) {
                unsigned a0 = h01h[mt][2 * kt],     a1 = h23h[mt][2 * kt];
                unsigned a2 = h01h[mt][2 * kt + 1], a3 = h23h[mt][2 * kt + 1];
                unsigned c0 = h01l[mt][2 * kt],     c1 = h23l[mt][2 * kt];
                unsigned c2 = h01l[mt][2 * kt + 1], c3 = h23l[mt][2 * kt + 1];
                mma_bf16(acc2[mt][ntb], a0, a1, a2, a3, bl0, bl1);
                mma_bf16(acc2[mt][ntb], c0, c1, c2, c3, bh0, bh1);
                mma_bf16(acc2[mt][ntb], a0, a1, a2, a3, bh0, bh1);
            }
        }
    }

    const int growBase = blockIdx.x * 256;
    const int i = growBase >> 10;
    #pragma unroll
    for (int mt = 0; mt < 2; mt++) {
        #pragma unroll
        for (int nt = 0; nt < 2; nt++) {
            #pragma unroll
            for (int e = 0; e < 4; e++) {
                int grow = growBase + rb0 + mt * 16 + g + ((e >= 2) ? 8 : 0);
                int j = grow & 1023;
                int col = nt * 8 + 2 * tg + (e & 1);
                g_aff[((size_t)i * 16 + col) * 1024 + j] = acc2[mt][nt][e] + bb2[col];
            }
        }
    }
}

// ---------------------------------------------------------------------------
// K3a: weighted logits W = aff * (Q K^T / 8) in place. 64x64 tiles (R11).
// ---------------------------------------------------------------------------
#define LGT_SMEM_U (4 * 2304)

__global__ void __launch_bounds__(256) k_logits()
{
    extern __shared__ unsigned smlu[];
    unsigned* Qh = smlu;          // [64][36]
    unsigned* Ql = Qh + 2304;
    unsigned* Kh = Ql + 2304;
    unsigned* Kl = Kh + 2304;

    const int gblk = blockIdx.z;
    const int i0 = blockIdx.y * 64, j0 = blockIdx.x * 64;
    const int tid = threadIdx.x, lane = tid & 31, wid = tid >> 5;
    const int g = lane >> 2, tg = lane & 3;
    const int mb = (wid >> 1) * 16, nw = wid & 1;
    const int larow = lane & 15, lcol4 = (lane >> 4) * 4;
    const int brow = lane & 7, bcolo = ((lane >> 3) & 1) * 4;

    #pragma unroll
    for (int it = 0; it < 2; it++) {
        int idx = tid + it * 256;
        int r = idx >> 3, c4 = (idx & 7) * 4;
        const size_t gi = (size_t)(i0 + r) * 512 + gblk * 32 + c4;
        const size_t gj = (size_t)(j0 + r) * 512 + gblk * 32 + c4;
        *(uint4*)&Qh[r * 36 + c4] = *(const uint4*)&g_qh[gi];
        *(uint4*)&Ql[r * 36 + c4] = *(const uint4*)&g_ql[gi];
        *(uint4*)&Kh[r * 36 + c4] = *(const uint4*)&g_kh[gj];
        *(uint4*)&Kl[r * 36 + c4] = *(const uint4*)&g_kl[gj];
    }
    __syncthreads();

    float cs[4][4] = {};
    #pragma unroll
    for (int kt = 0; kt < 4; kt++) {
        const int kb = kt * 8;
        unsigned ah[4], al[4];
        ldsm_x4(ah[0], ah[1], ah[2], ah[3], sptr(&Qh[(mb + larow) * 36 + kb + lcol4]));
        ldsm_x4(al[0], al[1], al[2], al[3], sptr(&Ql[(mb + larow) * 36 + kb + lcol4]));
        #pragma unroll
        for (int nt = 0; nt < 4; nt++) {
            const int nb = nw * 32 + nt * 8;
            unsigned bh0, bh1, bl0, bl1;
            ldsm_x2(bh0, bh1, sptr(&Kh[(nb + brow) * 36 + kb + bcolo]));
            ldsm_x2(bl0, bl1, sptr(&Kl[(nb + brow) * 36 + kb + bcolo]));
            mma_bf16(cs[nt], ah[0], ah[1], ah[2], ah[3], bl0, bl1);
            mma_bf16(cs[nt], al[0], al[1], al[2], al[3], bh0, bh1);
            mma_bf16(cs[nt], ah[0], ah[1], ah[2], ah[3], bh0, bh1);
        }
    }

    #pragma unroll
    for (int nt = 0; nt < 4; nt++) {
        const int col = nw * 32 + nt * 8 + 2 * tg;
        const int r0 = mb + g;
        float* p0 = &g_aff[(((size_t)(i0 + r0)) * 16 + gblk) * 1024 + j0 + col];
        float* p1 = &g_aff[(((size_t)(i0 + r0 + 8)) * 16 + gblk) * 1024 + j0 + col];
        float2 a0 = *(const float2*)p0;
        float2 a1 = *(const float2*)p1;
        *(float2*)p0 = make_float2(cs[nt][0] * 0.125f * a0.x, cs[nt][1] * 0.125f * a0.y);
        *(float2*)p1 = make_float2(cs[nt][2] * 0.125f * a1.x, cs[nt][3] * 0.125f * a1.y);
    }
}

// ---------------------------------------------------------------------------
// K3b: online softmax over W + 3-pass bf16 P@V. 32-row i-tiles (R11 winner).
// ---------------------------------------------------------------------------
#define AT2_SMEM_U (2 * 2304 + 2 * 1152 + 96)

__global__ void __launch_bounds__(256) k_attn2(
    const float* __restrict__ bout, float* __restrict__ out)
{
    extern __shared__ unsigned smau[];
    unsigned* Vh = smau;           // [j=64][36] (o-pairs)
    unsigned* Vl = Vh + 2304;
    unsigned* Ph = Vl + 2304;      // [i=32][36] (j-pairs)
    unsigned* Pl = Ph + 1152;
    float* m_s  = (float*)(Pl + 1152);   // [32]
    float* l_s  = m_s + 32;
    float* al_s = l_s + 32;

    const int gblk = blockIdx.y;
    const int i0 = blockIdx.x * 32;
    const int tid = threadIdx.x, lane = tid & 31, wid = tid >> 5;
    const int g = lane >> 2, tg = lane & 3;
    const int mb = (wid >> 2) * 16, nw = wid & 3;
    const int larow = lane & 15, lcol4 = (lane >> 4) * 4;

    if (tid < 32) { m_s[tid] = -1e30f; l_s[tid] = 0.f; }

    float co[2][4] = {};

    for (int c = 0; c < 16; c++) {
        const int j0 = c * 64;
        __syncthreads();

        #pragma unroll
        for (int it = 0; it < 2; it++) {
            int idx = tid + it * 256;
            int r = idx >> 3, c4 = (idx & 7) * 4;
            const size_t gv = (size_t)(j0 + r) * 512 + gblk * 32 + c4;
            *(uint4*)&Vh[r * 36 + c4] = *(const uint4*)&g_vh[gv];
            *(uint4*)&Vl[r * 36 + c4] = *(const uint4*)&g_vl[gv];
        }

        #pragma unroll
        for (int rr = 0; rr < 4; rr++) {
            const int row = wid * 4 + rr;
            float2 w2 = *(const float2*)&g_aff[(((size_t)(i0 + row)) * 16 + gblk) * 1024 + j0 + 2 * lane];
            float s0 = w2.x, s1 = w2.y;
            float mx = fmaxf(s0, s1);
            #pragma unroll
            for (int o = 16; o; o >>= 1) mx = fmaxf(mx, __shfl_xor_sync(0xffffffffu, mx, o));
            float mold = m_s[row];
            float mnew = fmaxf(mold, mx);
            float p0 = __expf(s0 - mnew), p1 = __expf(s1 - mnew);
            float su = p0 + p1;
            #pragma unroll
            for (int o = 16; o; o >>= 1) su += __shfl_xor_sync(0xffffffffu, su, o);
            if (lane == 0) {
                float alpha = __expf(mold - mnew);
                m_s[row] = mnew;
                al_s[row] = alpha;
                l_s[row] = l_s[row] * alpha + su;
            }
            unsigned ph, pl;
            pack2(p0, p1, ph, pl);
            Ph[row * 36 + lane] = ph;
            Pl[row * 36 + lane] = pl;
        }
        __syncthreads();

        {
            float a0 = al_s[mb + g], a1 = al_s[mb + g + 8];
            #pragma unroll
            for (int nt = 0; nt < 2; nt++) {
                co[nt][0] *= a0; co[nt][1] *= a0;
                co[nt][2] *= a1; co[nt][3] *= a1;
            }
            #pragma unroll
            for (int kt = 0; kt < 4; kt++) {
                const int kb = kt * 8;        // j-pair offset for P
                const int jb = kt * 16;       // j-row offset for V
                unsigned ah[4], al[4];
                ldsm_x4(ah[0], ah[1], ah[2], ah[3], sptr(&Ph[(mb + larow) * 36 + kb + lcol4]));
                ldsm_x4(al[0], al[1], al[2], al[3], sptr(&Pl[(mb + larow) * 36 + kb + lcol4]));
                #pragma unroll
                for (int nt = 0; nt < 2; nt++) {
                    const int vcol = nw * 8 + nt * 4;   // o-pair column
                    unsigned bh0, bh1, bl0, bl1;
                    ldsm_x2t(bh0, bh1, sptr(&Vh[(jb + larow) * 36 + vcol]));
                    ldsm_x2t(bl0, bl1, sptr(&Vl[(jb + larow) * 36 + vcol]));
                    mma_bf16(co[nt], ah[0], ah[1], ah[2], ah[3], bl0, bl1);
                    mma_bf16(co[nt], al[0], al[1], al[2], al[3], bh0, bh1);
                    mma_bf16(co[nt], ah[0], ah[1], ah[2], ah[3], bh0, bh1);
                }
            }
        }
    }
    __syncthreads();

    {
        float inv0 = 1.0f / l_s[mb + g];
        float inv1 = 1.0f / l_s[mb + g + 8];
        #pragma unroll
        for (int nt = 0; nt < 2; nt++) {
            const int cl = nw * 16 + nt * 8 + 2 * tg;
            const int col = gblk * 64 + cl;
            float b0 = bout[col], b1 = bout[col + 1];
            int r0 = i0 + mb + g;
            *(float2*)&out[(size_t)r0 * 1024 + col] =
                make_float2(co[nt][0] * inv0 + b0, co[nt][1] * inv0 + b1);
            *(float2*)&out[(size_t)(r0 + 8) * 1024 + col] =
                make_float2(co[nt][2] * inv1 + b0, co[nt][3] * inv1 + b1);
        }
    }
}

// ---------------------------------------------------------------------------
extern "C" void kernel_launch(void* const* d_in, const int* in_sizes, int n_in,
                              void* d_out, int out_size) {
    const float* roi  = (const float*)d_in[0];
    const float* pe   = (const float*)d_in[1];
    const float* W1   = (const float*)d_in[2];
    const float* b1   = (const float*)d_in[3];
    const float* W2   = (const float*)d_in[4];
    const float* b2   = (const float*)d_in[5];
    const float* Wq   = (const float*)d_in[6];
    const float* bq   = (const float*)d_in[7];
    const float* Wk   = (const float*)d_in[8];
    const float* bk   = (const float*)d_in[9];
    const float* Wout = (const float*)d_in[10];
    const float* bout = (const float*)d_in[11];
    float* out = (float*)d_out;

    const int g3_smem = (4 * K1_AS + 4 * K1_BS) * (int)sizeof(unsigned);
    const int pe_smem = (17408 + 4352 + 80) * (int)sizeof(float) + 1152 * (int)sizeof(unsigned);
    const int lg_smem = LGT_SMEM_U * (int)sizeof(unsigned);
    const int at_smem = AT2_SMEM_U * (int)sizeof(unsigned);
    cudaFuncSetAttribute(k_gemm3,  cudaFuncAttributeMaxDynamicSharedMemorySize, g3_smem);
    cudaFuncSetAttribute(k_pe,     cudaFuncAttributeMaxDynamicSharedMemorySize, pe_smem);
    cudaFuncSetAttribute(k_logits, cudaFuncAttributeMaxDynamicSharedMemorySize, lg_smem);
    cudaFuncSetAttribute(k_attn2,  cudaFuncAttributeMaxDynamicSharedMemorySize, at_smem);

    k_gemm3<<<dim3(8, 8, 3), 256, g3_smem>>>(roi, Wq, bq, Wk, bk, Wout);
    k_pe<<<(Nn * Nn) / 256, 256, pe_smem>>>(pe, W1, b1, W2, b2);
    k_logits<<<dim3(16, 16, 16), 256, lg_smem>>>();
    k_attn2<<<dim3(Nn / 32, Gg), 256, at_smem>>>(bout, out);
}

// round 17
// speedup vs baseline: 1.3841x; 1.1502x over previous
#include <cuda_runtime.h>
#include <cuda_bf16.h>
#include <math.h>

#define Nn 1024
#define Dd 1024
#define Gg 16

// Scratch (allocation-free rule: __device__ globals). Packed bf16 hi/lo pairs.
__device__ unsigned g_qh[Nn * 512], g_ql[Nn * 512];   // q [i][d/2]
__device__ unsigned g_kh[Nn * 512], g_kl[Nn * 512];   // k [j][d/2]
__device__ unsigned g_vh[Nn * 512], g_vl[Nn * 512];   // v2 [j][o/2]
__device__ float g_aff[(size_t)Nn * Gg * Nn];         // aff -> overwritten with weighted logits

__device__ __forceinline__ unsigned f2tf(float x) {
    unsigned u; asm("cvt.rna.tf32.f32 %0, %1;" : "=r"(u) : "f"(x)); return u;
}
__device__ __forceinline__ unsigned u2tf(unsigned x) {
    unsigned u; asm("cvt.rna.tf32.f32 %0, %1;" : "=r"(u) : "f"(__uint_as_float(x))); return u;
}
__device__ __forceinline__ float ftanh(float x) {
    float y; asm("tanh.approx.f32 %0, %1;" : "=f"(y) : "f"(x)); return y;
}
__device__ __forceinline__ void mma_tf32(float* c,
    unsigned a0, unsigned a1, unsigned a2, unsigned a3,
    unsigned b0, unsigned b1) {
    asm volatile(
        "mma.sync.aligned.m16n8k8.row.col.f32.tf32.tf32.f32 "
        "{%0,%1,%2,%3}, {%4,%5,%6,%7}, {%8,%9}, {%0,%1,%2,%3};\n"
        : "+f"(c[0]), "+f"(c[1]), "+f"(c[2]), "+f"(c[3])
        : "r"(a0), "r"(a1), "r"(a2), "r"(a3), "r"(b0), "r"(b1));
}
__device__ __forceinline__ void mma_bf16(float* c,
    unsigned a0, unsigned a1, unsigned a2, unsigned a3,
    unsigned b0, unsigned b1) {
    asm volatile(
        "mma.sync.aligned.m16n8k16.row.col.f32.bf16.bf16.f32 "
        "{%0,%1,%2,%3}, {%4,%5,%6,%7}, {%8,%9}, {%0,%1,%2,%3};\n"
        : "+f"(c[0]), "+f"(c[1]), "+f"(c[2]), "+f"(c[3])
        : "r"(a0), "r"(a1), "r"(a2), "r"(a3), "r"(b0), "r"(b1));
}
__device__ __forceinline__ unsigned sptr(const void* p) {
    return (unsigned)__cvta_generic_to_shared(p);
}
__device__ __forceinline__ void ldsm_x4(unsigned& r0, unsigned& r1, unsigned& r2, unsigned& r3, unsigned a) {
    asm volatile("ldmatrix.sync.aligned.m8n8.x4.shared.b16 {%0,%1,%2,%3}, [%4];"
        : "=r"(r0), "=r"(r1), "=r"(r2), "=r"(r3) : "r"(a));
}
__device__ __forceinline__ void ldsm_x2(unsigned& r0, unsigned& r1, unsigned a) {
    asm volatile("ldmatrix.sync.aligned.m8n8.x2.shared.b16 {%0,%1}, [%2];"
        : "=r"(r0), "=r"(r1) : "r"(a));
}
__device__ __forceinline__ void ldsm_x2t(unsigned& r0, unsigned& r1, unsigned a) {
    asm volatile("ldmatrix.sync.aligned.m8n8.x2.trans.shared.b16 {%0,%1}, [%2];"
        : "=r"(r0), "=r"(r1) : "r"(a));
}
__device__ __forceinline__ void cpa16(unsigned dst, const void* src) {
    asm volatile("cp.async.ca.shared.global [%0], [%1], 16;" :: "r"(dst), "l"(src));
}
#define CP_COMMIT asm volatile("cp.async.commit_group;")
#define CP_WAIT0  asm volatile("cp.async.wait_group 0;")

// bf16 hi/lo split of a pair (a->low half, b->high half)
__device__ __forceinline__ void pack2(float a, float b, unsigned& hi, unsigned& lo) {
    __nv_bfloat16 ba = __float2bfloat16(a), bb = __float2bfloat16(b);
    hi = ((unsigned)__bfloat16_as_ushort(bb) << 16) | (unsigned)__bfloat16_as_ushort(ba);
    __nv_bfloat16 la = __float2bfloat16(a - __bfloat162float(ba));
    __nv_bfloat16 lb = __float2bfloat16(b - __bfloat162float(bb));
    lo = ((unsigned)__bfloat16_as_ushort(lb) << 16) | (unsigned)__bfloat16_as_ushort(la);
}

#define K1_AS 1536   // 128*12 b32 per A buffer
#define K1_BS 1088   // 16*68 b32 per B buffer

// ---------------------------------------------------------------------------
// gemm3 body: one 128x128 tile of one of three 1024^3 GEMMs (R11 winner).
// ---------------------------------------------------------------------------
__device__ void gemm3_body(
    int z, int bx, int by, char* smraw,
    const float* __restrict__ roi,
    const float* __restrict__ Wq, const float* __restrict__ bq,
    const float* __restrict__ Wk, const float* __restrict__ bk,
    const float* __restrict__ Wout)
{
    unsigned* smu = (unsigned*)smraw;
    unsigned* Ah = smu;
    unsigned* Al = Ah + 2 * K1_AS;
    unsigned* Bh = Al + 2 * K1_AS;
    unsigned* Bl = Bh + 2 * K1_BS;

    const int rowBase = by * 128, colBase = bx * 128;
    const int tid = threadIdx.x, lane = tid & 31, wid = tid >> 5;
    const int g = lane >> 2, tg = lane & 3;
    const int m_off = (wid >> 2) * 64, n_off = (wid & 3) * 32;
    const float* Bm = (z == 0) ? Wq : (z == 1) ? Wk : Wout;

    float acc[4][4][4] = {};
    const int larow = lane & 15, lcol4 = (lane >> 4) * 4;
    float4 aReg[2], bReg[2];

    {
        const int k0 = 0;
        #pragma unroll
        for (int it = 0; it < 2; it++) {
            int idx = tid + it * 256;
            int r = idx >> 2, c4 = idx & 3;
            aReg[it] = *(const float4*)&roi[(size_t)(rowBase + r) * 1024 + k0 + c4 * 4];
        }
        #pragma unroll
        for (int it = 0; it < 2; it++) {
            int idx = tid + it * 256;
            int kr = idx >> 5, c4 = idx & 31;
            int col = colBase + c4 * 4;
            const float* src;
            if (z < 2) src = &Bm[(size_t)(k0 + kr) * 1024 + col];
            else { int gg = col >> 6, oo = col & 63; src = &Bm[((size_t)gg * 1024 + (k0 + kr)) * 64 + oo]; }
            bReg[it] = *(const float4*)src;
        }
        #pragma unroll
        for (int it = 0; it < 2; it++) {
            int idx = tid + it * 256;
            int r = idx >> 2, c4 = idx & 3;
            unsigned h0, l0, h1, l1;
            pack2(aReg[it].x, aReg[it].y, h0, l0);
            pack2(aReg[it].z, aReg[it].w, h1, l1);
            Ah[r * 12 + c4 * 2] = h0; Ah[r * 12 + c4 * 2 + 1] = h1;
            Al[r * 12 + c4 * 2] = l0; Al[r * 12 + c4 * 2 + 1] = l1;
        }
        #pragma unroll
        for (int it = 0; it < 2; it++) {
            int idx = tid + it * 256;
            int kr = idx >> 5, c4 = idx & 31;
            unsigned h0, l0, h1, l1;
            pack2(bReg[it].x, bReg[it].y, h0, l0);
            pack2(bReg[it].z, bReg[it].w, h1, l1);
            Bh[kr * 68 + c4 * 2] = h0; Bh[kr * 68 + c4 * 2 + 1] = h1;
            Bl[kr * 68 + c4 * 2] = l0; Bl[kr * 68 + c4 * 2 + 1] = l1;
        }
    }
    __syncthreads();

    for (int s = 0; s < 64; s++) {
        const int buf = s & 1;
        if (s < 63) {
            const int k0 = (s + 1) * 16;
            #pragma unroll
            for (int it = 0; it < 2; it++) {
                int idx = tid + it * 256;
                int r = idx >> 2, c4 = idx & 3;
                aReg[it] = *(const float4*)&roi[(size_t)(rowBase + r) * 1024 + k0 + c4 * 4];
            }
            #pragma unroll
            for (int it = 0; it < 2; it++) {
                int idx = tid + it * 256;
                int kr = idx >> 5, c4 = idx & 31;
                int col = colBase + c4 * 4;
                const float* src;
                if (z < 2) src = &Bm[(size_t)(k0 + kr) * 1024 + col];
                else { int gg = col >> 6, oo = col & 63; src = &Bm[((size_t)gg * 1024 + (k0 + kr)) * 64 + oo]; }
                bReg[it] = *(const float4*)src;
            }
        }

        const unsigned* ah_b = Ah + buf * K1_AS;
        const unsigned* al_b = Al + buf * K1_AS;
        const unsigned* bh_b = Bh + buf * K1_BS;
        const unsigned* bl_b = Bl + buf * K1_BS;

        unsigned ah[4][4], al[4][4];
        #pragma unroll
        for (int mt = 0; mt < 4; mt++) {
            const int rb = m_off + mt * 16;
            ldsm_x4(ah[mt][0], ah[mt][1], ah[mt][2], ah[mt][3],
                    sptr(&ah_b[(rb + larow) * 12 + lcol4]));
            ldsm_x4(al[mt][0], al[mt][1], al[mt][2], al[mt][3],
                    sptr(&al_b[(rb + larow) * 12 + lcol4]));
        }
        #pragma unroll
        for (int nt = 0; nt < 4; nt++) {
            const int nbc = (n_off >> 1) + nt * 4;
            unsigned bh0, bh1, bl0, bl1;
            ldsm_x2t(bh0, bh1, sptr(&bh_b[larow * 68 + nbc]));
            ldsm_x2t(bl0, bl1, sptr(&bl_b[larow * 68 + nbc]));
            #pragma unroll
            for (int mt = 0; mt < 4; mt++) {
                mma_bf16(acc[mt][nt], ah[mt][0], ah[mt][1], ah[mt][2], ah[mt][3], bl0, bl1);
                mma_bf16(acc[mt][nt], al[mt][0], al[mt][1], al[mt][2], al[mt][3], bh0, bh1);
                mma_bf16(acc[mt][nt], ah[mt][0], ah[mt][1], ah[mt][2], ah[mt][3], bh0, bh1);
            }
        }

        if (s < 63) {
            unsigned* AhN = Ah + (buf ^ 1) * K1_AS;
            unsigned* AlN = Al + (buf ^ 1) * K1_AS;
            unsigned* BhN = Bh + (buf ^ 1) * K1_BS;
            unsigned* BlN = Bl + (buf ^ 1) * K1_BS;
            #pragma unroll
            for (int it = 0; it < 2; it++) {
                int idx = tid + it * 256;
                int r = idx >> 2, c4 = idx & 3;
                unsigned h0, l0, h1, l1;
                pack2(aReg[it].x, aReg[it].y, h0, l0);
                pack2(aReg[it].z, aReg[it].w, h1, l1);
                AhN[r * 12 + c4 * 2] = h0; AhN[r * 12 + c4 * 2 + 1] = h1;
                AlN[r * 12 + c4 * 2] = l0; AlN[r * 12 + c4 * 2 + 1] = l1;
            }
            #pragma unroll
            for (int it = 0; it < 2; it++) {
                int idx = tid + it * 256;
                int kr = idx >> 5, c4 = idx & 31;
                unsigned h0, l0, h1, l1;
                pack2(bReg[it].x, bReg[it].y, h0, l0);
                pack2(bReg[it].z, bReg[it].w, h1, l1);
                BhN[kr * 68 + c4 * 2] = h0; BhN[kr * 68 + c4 * 2 + 1] = h1;
                BlN[kr * 68 + c4 * 2] = l0; BlN[kr * 68 + c4 * 2 + 1] = l1;
            }
        }
        __syncthreads();
    }

    #pragma unroll
    for (int mt = 0; mt < 4; mt++) {
        #pragma unroll
        for (int nt = 0; nt < 4; nt++) {
            const int row = rowBase + m_off + mt * 16 + g;
            const int col = colBase + n_off + nt * 8 + 2 * tg;
            const size_t p0 = (size_t)row * 512 + (col >> 1);
            const size_t p1 = (size_t)(row + 8) * 512 + (col >> 1);
            float v0 = acc[mt][nt][0], v1 = acc[mt][nt][1];
            float v2 = acc[mt][nt][2], v3 = acc[mt][nt][3];
            unsigned h, l;
            if (z == 0) {
                float b0 = bq[col], b1 = bq[col + 1];
                pack2(v0 + b0, v1 + b1, h, l); g_qh[p0] = h; g_ql[p0] = l;
                pack2(v2 + b0, v3 + b1, h, l); g_qh[p1] = h; g_ql[p1] = l;
            } else if (z == 1) {
                float b0 = bk[col], b1 = bk[col + 1];
                pack2(v0 + b0, v1 + b1, h, l); g_kh[p0] = h; g_kl[p0] = l;
                pack2(v2 + b0, v3 + b1, h, l); g_kh[p1] = h; g_kl[p1] = l;
            } else {
                pack2(v0, v1, h, l); g_vh[p0] = h; g_vl[p0] = l;
                pack2(v2, v3, h, l); g_vh[p1] = h; g_vl[p1] = l;
            }
        }
    }
}

// ---------------------------------------------------------------------------
// pe body: 256 rows of the PE MLP (R16 version).
// ---------------------------------------------------------------------------
__device__ void pe_body(
    int bx, char* smraw,
    const float* __restrict__ pe,
    const float* __restrict__ W1, const float* __restrict__ b1,
    const float* __restrict__ W2, const float* __restrict__ b2)
{
    float* sm2 = (float*)smraw;
    float* H    = sm2;                     // 256*68 (raw fp32 pe tile)
    float* W1sT = H + 17408;               // [n=64][k] stride 68
    unsigned* W2h = (unsigned*)(W1sT + 4352);  // [n=16][k-pairs] stride 36 = 576
    unsigned* W2l = W2h + 576;
    float* bb1  = (float*)(W2l + 576);     // 64
    float* bb2  = bb1 + 64;                // 16

    const int tid = threadIdx.x, lane = tid & 31, wid = tid >> 5;
    const int g = lane >> 2, tg = lane & 3;
    const int arow = lane & 15, acolo = (lane >> 4) * 4;
    const int brow = lane & 7, bcolo = ((lane >> 3) & 1) * 4;

    const size_t base = (size_t)bx * 256 * 64;
    #pragma unroll
    for (int it = 0; it < 16; it++) {
        int idx = tid + it * 256;
        int r = idx >> 4, c4 = idx & 15;
        cpa16(sptr(&H[r * 68 + c4 * 4]), &pe[base + (size_t)idx * 4]);
    }
    CP_COMMIT;

    for (int l = tid; l < 4096; l += 256) {
        int k = l >> 6, n = l & 63;
        W1sT[n * 68 + k] = __uint_as_float(f2tf(W1[l]));
    }
    for (int l = tid; l < 512; l += 256) {     // 16 n x 32 k-pairs
        int n = l >> 5, kp = l & 31;
        float a = W2[(size_t)(2 * kp) * 16 + n];
        float b = W2[(size_t)(2 * kp + 1) * 16 + n];
        unsigned h, lo;
        pack2(a, b, h, lo);
        W2h[n * 36 + kp] = h; W2l[n * 36 + kp] = lo;
    }
    if (tid < 64) bb1[tid] = b1[tid];
    if (tid < 16) bb2[tid] = b2[tid];

    CP_WAIT0;
    __syncthreads();

    const int rb0 = wid * 32;
    float acc[2][8][4] = {};
    #pragma unroll
    for (int kt = 0; kt < 8; kt++) {
        const int kb = kt * 8;
        unsigned a[2][4];
        #pragma unroll
        for (int mt = 0; mt < 2; mt++) {
            ldsm_x4(a[mt][0], a[mt][1], a[mt][2], a[mt][3],
                    sptr(&H[(rb0 + mt * 16 + arow) * 68 + kb + acolo]));
            a[mt][0] = u2tf(a[mt][0]); a[mt][1] = u2tf(a[mt][1]);
            a[mt][2] = u2tf(a[mt][2]); a[mt][3] = u2tf(a[mt][3]);
        }
        #pragma unroll
        for (int nt = 0; nt < 8; nt++) {
            unsigned b0, b1r;
            ldsm_x2(b0, b1r, sptr(&W1sT[(nt * 8 + brow) * 68 + kb + bcolo]));
            mma_tf32(acc[0][nt], a[0][0], a[0][1], a[0][2], a[0][3], b0, b1r);
            mma_tf32(acc[1][nt], a[1][0], a[1][1], a[1][2], a[1][3], b0, b1r);
        }
    }

    unsigned h01h[2][8], h01l[2][8], h23h[2][8], h23l[2][8];
    #pragma unroll
    for (int mt = 0; mt < 2; mt++) {
        #pragma unroll
        for (int nt = 0; nt < 8; nt++) {
            const int col = nt * 8 + 2 * tg;
            float h0 = ftanh(acc[mt][nt][0] + bb1[col]);
            float h1 = ftanh(acc[mt][nt][1] + bb1[col + 1]);
            float h2 = ftanh(acc[mt][nt][2] + bb1[col]);
            float h3 = ftanh(acc[mt][nt][3] + bb1[col + 1]);
            pack2(h0, h1, h01h[mt][nt], h01l[mt][nt]);
            pack2(h2, h3, h23h[mt][nt], h23l[mt][nt]);
        }
    }

    float acc2[2][2][4] = {};
    #pragma unroll
    for (int kt = 0; kt < 4; kt++) {
        const int kb = kt * 8;
        #pragma unroll
        for (int ntb = 0; ntb < 2; ntb++) {
            unsigned bh0, bh1, bl0, bl1;
            ldsm_x2(bh0, bh1, sptr(&W2h[(ntb * 8 + brow) * 36 + kb + bcolo]));
            ldsm_x2(bl0, bl1, sptr(&W2l[(ntb * 8 + brow) * 36 + kb + bcolo]));
            #pragma unroll
            for (int mt = 0; mt < 2; mt++) {
                unsigned a0 = h01h[mt][2 * kt],     a1 = h23h[mt][2 * kt];
                unsigned a2 = h01h[mt][2 * kt + 1], a3 = h23h[mt][2 * kt + 1];
                unsigned c0 = h01l[mt][2 * kt],     c1 = h23l[mt][2 * kt];
                unsigned c2 = h01l[mt][2 * kt + 1], c3 = h23l[mt][2 * kt + 1];
                mma_bf16(acc2[mt][ntb], a0, a1, a2, a3, bl0, bl1);
                mma_bf16(acc2[mt][ntb], c0, c1, c2, c3, bh0, bh1);
                mma_bf16(acc2[mt][ntb], a0, a1, a2, a3, bh0, bh1);
            }
        }
    }

    const int growBase = bx * 256;
    const int i = growBase >> 10;
    #pragma unroll
    for (int mt = 0; mt < 2; mt++) {
        #pragma unroll
        for (int nt = 0; nt < 2; nt++) {
            #pragma unroll
            for (int e = 0; e < 4; e++) {
                int grow = growBase + rb0 + mt * 16 + g + ((e >= 2) ? 8 : 0);
                int j = grow & 1023;
                int col = nt * 8 + 2 * tg + (e & 1);
                g_aff[((size_t)i * 16 + col) * 1024 + j] = acc2[mt][nt][e] + bb2[col];
            }
        }
    }
}

// ---------------------------------------------------------------------------
// K1+K2 fused launch: blocks [0,192) = gemm3 tiles, [192, 4288) = pe tiles.
// ---------------------------------------------------------------------------
__global__ void __launch_bounds__(256, 2) k_phase1(
    const float* __restrict__ roi,
    const float* __restrict__ Wq, const float* __restrict__ bq,
    const float* __restrict__ Wk, const float* __restrict__ bk,
    const float* __restrict__ Wout,
    const float* __restrict__ pe,
    const float* __restrict__ W1, const float* __restrict__ b1,
    const float* __restrict__ W2, const float* __restrict__ b2)
{
    extern __shared__ char smraw[];
    const int bid = blockIdx.x;
    if (bid < 192) {
        const int z = bid >> 6, rem = bid & 63;
        gemm3_body(z, rem & 7, rem >> 3, smraw, roi, Wq, bq, Wk, bk, Wout);
    } else {
        pe_body(bid - 192, smraw, pe, W1, b1, W2, b2);
    }
}

// ---------------------------------------------------------------------------
// K3a: weighted logits W = aff * (Q K^T / 8) in place. 64x64 tiles (R11).
// ---------------------------------------------------------------------------
#define LGT_SMEM_U (4 * 2304)

__global__ void __launch_bounds__(256) k_logits()
{
    extern __shared__ unsigned smlu[];
    unsigned* Qh = smlu;          // [64][36]
    unsigned* Ql = Qh + 2304;
    unsigned* Kh = Ql + 2304;
    unsigned* Kl = Kh + 2304;

    const int gblk = blockIdx.z;
    const int i0 = blockIdx.y * 64, j0 = blockIdx.x * 64;
    const int tid = threadIdx.x, lane = tid & 31, wid = tid >> 5;
    const int g = lane >> 2, tg = lane & 3;
    const int mb = (wid >> 1) * 16, nw = wid & 1;
    const int larow = lane & 15, lcol4 = (lane >> 4) * 4;
    const int brow = lane & 7, bcolo = ((lane >> 3) & 1) * 4;

    #pragma unroll
    for (int it = 0; it < 2; it++) {
        int idx = tid + it * 256;
        int r = idx >> 3, c4 = (idx & 7) * 4;
        const size_t gi = (size_t)(i0 + r) * 512 + gblk * 32 + c4;
        const size_t gj = (size_t)(j0 + r) * 512 + gblk * 32 + c4;
        *(uint4*)&Qh[r * 36 + c4] = *(const uint4*)&g_qh[gi];
        *(uint4*)&Ql[r * 36 + c4] = *(const uint4*)&g_ql[gi];
        *(uint4*)&Kh[r * 36 + c4] = *(const uint4*)&g_kh[gj];
        *(uint4*)&Kl[r * 36 + c4] = *(const uint4*)&g_kl[gj];
    }
    __syncthreads();

    float cs[4][4] = {};
    #pragma unroll
    for (int kt = 0; kt < 4; kt++) {
        const int kb = kt * 8;
        unsigned ah[4], al[4];
        ldsm_x4(ah[0], ah[1], ah[2], ah[3], sptr(&Qh[(mb + larow) * 36 + kb + lcol4]));
        ldsm_x4(al[0], al[1], al[2], al[3], sptr(&Ql[(mb + larow) * 36 + kb + lcol4]));
        #pragma unroll
        for (int nt = 0; nt < 4; nt++) {
            const int nb = nw * 32 + nt * 8;
            unsigned bh0, bh1, bl0, bl1;
            ldsm_x2(bh0, bh1, sptr(&Kh[(nb + brow) * 36 + kb + bcolo]));
            ldsm_x2(bl0, bl1, sptr(&Kl[(nb + brow) * 36 + kb + bcolo]));
            mma_bf16(cs[nt], ah[0], ah[1], ah[2], ah[3], bl0, bl1);
            mma_bf16(cs[nt], al[0], al[1], al[2], al[3], bh0, bh1);
            mma_bf16(cs[nt], ah[0], ah[1], ah[2], ah[3], bh0, bh1);
        }
    }

    #pragma unroll
    for (int nt = 0; nt < 4; nt++) {
        const int col = nw * 32 + nt * 8 + 2 * tg;
        const int r0 = mb + g;
        float* p0 = &g_aff[(((size_t)(i0 + r0)) * 16 + gblk) * 1024 + j0 + col];
        float* p1 = &g_aff[(((size_t)(i0 + r0 + 8)) * 16 + gblk) * 1024 + j0 + col];
        float2 a0 = *(const float2*)p0;
        float2 a1 = *(const float2*)p1;
        *(float2*)p0 = make_float2(cs[nt][0] * 0.125f * a0.x, cs[nt][1] * 0.125f * a0.y);
        *(float2*)p1 = make_float2(cs[nt][2] * 0.125f * a1.x, cs[nt][3] * 0.125f * a1.y);
    }
}

// ---------------------------------------------------------------------------
// K3b: online softmax over W + 3-pass bf16 P@V. 32-row i-tiles (R11 winner).
// ---------------------------------------------------------------------------
#define AT2_SMEM_U (2 * 2304 + 2 * 1152 + 96)

__global__ void __launch_bounds__(256) k_attn2(
    const float* __restrict__ bout, float* __restrict__ out)
{
    extern __shared__ unsigned smau[];
    unsigned* Vh = smau;           // [j=64][36] (o-pairs)
    unsigned* Vl = Vh + 2304;
    unsigned* Ph = Vl + 2304;      // [i=32][36] (j-pairs)
    unsigned* Pl = Ph + 1152;
    float* m_s  = (float*)(Pl + 1152);   // [32]
    float* l_s  = m_s + 32;
    float* al_s = l_s + 32;

    const int gblk = blockIdx.y;
    const int i0 = blockIdx.x * 32;
    const int tid = threadIdx.x, lane = tid & 31, wid = tid >> 5;
    const int g = lane >> 2, tg = lane & 3;
    const int mb = (wid >> 2) * 16, nw = wid & 3;
    const int larow = lane & 15, lcol4 = (lane >> 4) * 4;

    if (tid < 32) { m_s[tid] = -1e30f; l_s[tid] = 0.f; }

    float co[2][4] = {};

    for (int c = 0; c < 16; c++) {
        const int j0 = c * 64;
        __syncthreads();

        #pragma unroll
        for (int it = 0; it < 2; it++) {
            int idx = tid + it * 256;
            int r = idx >> 3, c4 = (idx & 7) * 4;
            const size_t gv = (size_t)(j0 + r) * 512 + gblk * 32 + c4;
            *(uint4*)&Vh[r * 36 + c4] = *(const uint4*)&g_vh[gv];
            *(uint4*)&Vl[r * 36 + c4] = *(const uint4*)&g_vl[gv];
        }

        #pragma unroll
        for (int rr = 0; rr < 4; rr++) {
            const int row = wid * 4 + rr;
            float2 w2 = *(const float2*)&g_aff[(((size_t)(i0 + row)) * 16 + gblk) * 1024 + j0 + 2 * lane];
            float s0 = w2.x, s1 = w2.y;
            float mx = fmaxf(s0, s1);
            #pragma unroll
            for (int o = 16; o; o >>= 1) mx = fmaxf(mx, __shfl_xor_sync(0xffffffffu, mx, o));
            float mold = m_s[row];
            float mnew = fmaxf(mold, mx);
            float p0 = __expf(s0 - mnew), p1 = __expf(s1 - mnew);
            float su = p0 + p1;
            #pragma unroll
            for (int o = 16; o; o >>= 1) su += __shfl_xor_sync(0xffffffffu, su, o);
            if (lane == 0) {
                float alpha = __expf(mold - mnew);
                m_s[row] = mnew;
                al_s[row] = alpha;
                l_s[row] = l_s[row] * alpha + su;
            }
            unsigned ph, pl;
            pack2(p0, p1, ph, pl);
            Ph[row * 36 + lane] = ph;
            Pl[row * 36 + lane] = pl;
        }
        __syncthreads();

        {
            float a0 = al_s[mb + g], a1 = al_s[mb + g + 8];
            #pragma unroll
            for (int nt = 0; nt < 2; nt++) {
                co[nt][0] *= a0; co[nt][1] *= a0;
                co[nt][2] *= a1; co[nt][3] *= a1;
            }
            #pragma unroll
            for (int kt = 0; kt < 4; kt++) {
                const int kb = kt * 8;        // j-pair offset for P
                const int jb = kt * 16;       // j-row offset for V
                unsigned ah[4], al[4];
                ldsm_x4(ah[0], ah[1], ah[2], ah[3], sptr(&Ph[(mb + larow) * 36 + kb + lcol4]));
                ldsm_x4(al[0], al[1], al[2], al[3], sptr(&Pl[(mb + larow) * 36 + kb + lcol4]));
                #pragma unroll
                for (int nt = 0; nt < 2; nt++) {
                    const int vcol = nw * 8 + nt * 4;   // o-pair column
                    unsigned bh0, bh1, bl0, bl1;
                    ldsm_x2t(bh0, bh1, sptr(&Vh[(jb + larow) * 36 + vcol]));
                    ldsm_x2t(bl0, bl1, sptr(&Vl[(jb + larow) * 36 + vcol]));
                    mma_bf16(co[nt], ah[0], ah[1], ah[2], ah[3], bl0, bl1);
                    mma_bf16(co[nt], al[0], al[1], al[2], al[3], bh0, bh1);
                    mma_bf16(co[nt], ah[0], ah[1], ah[2], ah[3], bh0, bh1);
                }
            }
        }
    }
    __syncthreads();

    {
        float inv0 = 1.0f / l_s[mb + g];
        float inv1 = 1.0f / l_s[mb + g + 8];
        #pragma unroll
        for (int nt = 0; nt < 2; nt++) {
            const int cl = nw * 16 + nt * 8 + 2 * tg;
            const int col = gblk * 64 + cl;
            float b0 = bout[col], b1 = bout[col + 1];
            int r0 = i0 + mb + g;
            *(float2*)&out[(size_t)r0 * 1024 + col] =
                make_float2(co[nt][0] * inv0 + b0, co[nt][1] * inv0 + b1);
            *(float2*)&out[(size_t)(r0 + 8) * 1024 + col] =
                make_float2(co[nt][2] * inv1 + b0, co[nt][3] * inv1 + b1);
        }
    }
}

// ---------------------------------------------------------------------------
extern "C" void kernel_launch(void* const* d_in, const int* in_sizes, int n_in,
                              void* d_out, int out_size) {
    const float* roi  = (const float*)d_in[0];
    const float* pe   = (const float*)d_in[1];
    const float* W1   = (const float*)d_in[2];
    const float* b1   = (const float*)d_in[3];
    const float* W2   = (const float*)d_in[4];
    const float* b2   = (const float*)d_in[5];
    const float* Wq   = (const float*)d_in[6];
    const float* bq   = (const float*)d_in[7];
    const float* Wk   = (const float*)d_in[8];
    const float* bk   = (const float*)d_in[9];
    const float* Wout = (const float*)d_in[10];
    const float* bout = (const float*)d_in[11];
    float* out = (float*)d_out;

    const int ph1_smem = (17408 + 4352 + 80) * (int)sizeof(float) + 1152 * (int)sizeof(unsigned);  // ~90KB (pe path; >= gemm3's 42KB)
    const int lg_smem  = LGT_SMEM_U * (int)sizeof(unsigned);
    const int at_smem  = AT2_SMEM_U * (int)sizeof(unsigned);
    cudaFuncSetAttribute(k_phase1, cudaFuncAttributeMaxDynamicSharedMemorySize, ph1_smem);
    cudaFuncSetAttribute(k_logits, cudaFuncAttributeMaxDynamicSharedMemorySize, lg_smem);
    cudaFuncSetAttribute(k_attn2,  cudaFuncAttributeMaxDynamicSharedMemorySize, at_smem);

    k_phase1<<<192 + 4096, 256, ph1_smem>>>(roi, Wq, bq, Wk, bk, Wout, pe, W1, b1, W2, b2);
    k_logits<<<dim3(16, 16, 16), 256, lg_smem>>>();
    k_attn2<<<dim3(Nn / 32, Gg), 256, at_smem>>>(bout, out);
}